// round 11
// baseline (speedup 1.0000x reference)
#include <cuda_runtime.h>
#include <cstdint>

#define B_ 4
#define L_ 2048
#define D_ 1024
#define H_ 16
#define HD_ 64
#define M_ 8192

// ---------------- scratch ----------------
__device__ float g_h[M_ * D_];
__device__ float g_q[M_ * D_];
__device__ float g_k[M_ * D_];
__device__ float g_v[M_ * D_];       // V stored TRANSPOSED: [bh][dim][L]
__device__ float g_att[M_ * D_];
__device__ float g_y[M_ * D_];
__device__ float g_wqkv[3 * D_ * D_];
__device__ float g_wo4[D_ * D_];
__device__ int   g_len[B_];

// ---------------- helpers ----------------
__device__ __forceinline__ float tf32r(float x) {
    float y; asm("cvt.rna.tf32.f32 %0, %1;" : "=f"(y) : "f"(x)); return y;
}
__device__ __forceinline__ uint32_t fu(float x) { return __float_as_uint(x); }
#define CPA16(dst, src) asm volatile("cp.async.cg.shared.global [%0], [%1], 16;\n" ::"r"(dst), "l"(src))
#define CPA_COMMIT asm volatile("cp.async.commit_group;\n")

__device__ __forceinline__ void mma_tf32(float& c0, float& c1, float& c2, float& c3,
                                         uint32_t a0, uint32_t a1, uint32_t a2, uint32_t a3,
                                         uint32_t b0, uint32_t b1) {
    asm volatile(
        "mma.sync.aligned.m16n8k8.row.col.f32.tf32.tf32.f32 "
        "{%0,%1,%2,%3}, {%4,%5,%6,%7}, {%8,%9}, {%0,%1,%2,%3};\n"
        : "+f"(c0), "+f"(c1), "+f"(c2), "+f"(c3)
        : "r"(a0), "r"(a1), "r"(a2), "r"(a3), "r"(b0), "r"(b1));
}

// ---------------- mask -> lengths ----------------
__global__ void mask_len_kernel(const unsigned int* __restrict__ pw) {
    __shared__ int s_bad;
    int t = threadIdx.x;
    if (t == 0) s_bad = 0;
    if (t < B_) g_len[t] = L_;
    __syncthreads();
    int bad = 0;
    for (int i = t; i < (B_ * L_) / 4; i += 256) {
        unsigned v = pw[i];
        if (v != 0u && v != 1u && v != 0x3F800000u) bad = 1;
    }
    if (bad) atomicExch(&s_bad, 1);
    __syncthreads();
    if (s_bad) {
        const unsigned char* pb = (const unsigned char*)pw;
        for (int i = t; i < B_ * L_; i += 256)
            if (pb[i]) atomicMin(&g_len[i >> 11], i & (L_ - 1));
    } else {
        for (int i = t; i < B_ * L_; i += 256)
            if (pw[i]) atomicMin(&g_len[i >> 11], i & (L_ - 1));
    }
}

// ---------------- weight tf32 pre-round ----------------
__global__ void wround_kernel(const float* __restrict__ a, const float* __restrict__ b,
                              const float* __restrict__ c, const float* __restrict__ d) {
    int i = blockIdx.x * 256 + threadIdx.x;
    g_wqkv[i]               = tf32r(a[i]);
    g_wqkv[D_ * D_ + i]     = tf32r(b[i]);
    g_wqkv[2 * D_ * D_ + i] = tf32r(c[i]);
    g_wo4[i]                = tf32r(d[i]);
}

// ---------------- LayerNorm ----------------
__global__ void ln_kernel(const float* __restrict__ x, const float* __restrict__ gamma,
                          const float* __restrict__ beta, float* __restrict__ out, int rnd) {
    __shared__ float red[8];
    __shared__ float s_mu, s_rs;
    int row = blockIdx.x;
    int t = threadIdx.x;
    float4 v = ((const float4*)(x + (size_t)row * D_))[t];
    float s = v.x + v.y + v.z + v.w;
    #pragma unroll
    for (int o = 16; o; o >>= 1) s += __shfl_xor_sync(0xffffffffu, s, o);
    if ((t & 31) == 0) red[t >> 5] = s;
    __syncthreads();
    if (t == 0) {
        float tot = 0.f;
        #pragma unroll
        for (int i = 0; i < 8; i++) tot += red[i];
        s_mu = tot * (1.0f / D_);
    }
    __syncthreads();
    float mu = s_mu;
    float dx = v.x - mu, dy = v.y - mu, dz = v.z - mu, dw = v.w - mu;
    float ss = dx * dx + dy * dy + dz * dz + dw * dw;
    #pragma unroll
    for (int o = 16; o; o >>= 1) ss += __shfl_xor_sync(0xffffffffu, ss, o);
    __syncthreads();
    if ((t & 31) == 0) red[t >> 5] = ss;
    __syncthreads();
    if (t == 0) {
        float tot = 0.f;
        #pragma unroll
        for (int i = 0; i < 8; i++) tot += red[i];
        s_rs = rsqrtf(tot * (1.0f / D_) + 1e-5f);
    }
    __syncthreads();
    float rs = s_rs;
    float4 gv = ((const float4*)gamma)[t];
    float4 bv = ((const float4*)beta)[t];
    float4 o4;
    o4.x = dx * rs * gv.x + bv.x;
    o4.y = dy * rs * gv.y + bv.y;
    o4.z = dz * rs * gv.z + bv.z;
    o4.w = dw * rs * gv.w + bv.w;
    if (rnd) { o4.x = tf32r(o4.x); o4.y = tf32r(o4.y); o4.z = tf32r(o4.z); o4.w = tf32r(o4.w); }
    ((float4*)(out + (size_t)row * D_))[t] = o4;
}

// ---------------- tf32 TC GEMM: C = A(MxK) x W(NxK)^T + bias ----------------
// Block 128x128, 8 warps of 64x32, BK=32, 3-stage cp.async. Swizzle at store;
// reads use parity-REORDERED chunk offsets (position c4+4(j^rp) -> phys chunk
// c4+4j, uniform across ALL threads of the mma -> correct slot pairing).
// Loop-invariant offsets, conflict-free. 2 CTAs/SM.
#define BK_ 32
#define NK_ (D_ / BK_)
__global__ __launch_bounds__(256, 2) void tgemm_kernel(
    const float* __restrict__ A, const float* __restrict__ W,
    const float* __restrict__ bias0, const float* __restrict__ bias1,
    const float* __restrict__ bias2, const float* __restrict__ res,
    float* __restrict__ C0, float* __restrict__ C1, float* __restrict__ C2,
    int mode) {
    extern __shared__ float4 Sm4[];     // [3][1024] A | [3][1024] B (B at +3072)
    int t = threadIdx.x, w = t >> 5, lane = t & 31;
    int r = lane >> 2, c4 = lane & 3;
    int rp = r & 1;
    int m0 = blockIdx.y * 128, n0 = blockIdx.x * 128;
    int wm = w >> 2, wn = w & 3;

    float acc[4][4][4] = {};

    // parity-reordered chunk offsets: jo[j] = 4*(j^rp)
    int jo0 = rp * 4, jo1 = 4 - rp * 4;

    // loop-invariant read offsets (float4 units), base includes c4
    int aOffL[4], aOffH[4], bOff[4];
    #pragma unroll
    for (int mt = 0; mt < 4; mt++) {
        aOffL[mt] = (wm * 64 + mt * 16 + r) * 8 + c4;
        aOffH[mt] = aOffL[mt] + 64;
    }
    #pragma unroll
    for (int nt = 0; nt < 4; nt++)
        bOff[nt] = (wn * 32 + nt * 8 + r) * 8 + c4;

    auto load_stage = [&](int st, int k0) {
        float4* sa = Sm4 + st * 1024;
        float4* sb = Sm4 + 3072 + st * 1024;
        #pragma unroll
        for (int i = 0; i < 8; i++) {
            int cid = t + i * 256;
            if (cid < 1024) {
                int row = cid >> 3, cc = cid & 7;
                uint32_t dst = (uint32_t)__cvta_generic_to_shared(
                    sa + row * 8 + (cc ^ ((row & 1) * 4)));
                CPA16(dst, A + (size_t)(m0 + row) * D_ + k0 + cc * 4);
            } else {
                int c2 = cid - 1024;
                int row = c2 >> 3, cc = c2 & 7;
                uint32_t dst = (uint32_t)__cvta_generic_to_shared(
                    sb + row * 8 + (cc ^ ((row & 1) * 4)));
                CPA16(dst, W + (size_t)(n0 + row) * D_ + k0 + cc * 4);
            }
        }
    };

    load_stage(0, 0);
    CPA_COMMIT;
    load_stage(1, BK_);
    CPA_COMMIT;

    int st = 0, stp = 2;
    #pragma unroll 1
    for (int kb = 0; kb < NK_; kb++) {
        if (kb + 1 < NK_) asm volatile("cp.async.wait_group 1;\n");
        else              asm volatile("cp.async.wait_group 0;\n");
        __syncthreads();
        if (kb + 2 < NK_) {
            load_stage(stp, (kb + 2) * BK_);
            CPA_COMMIT;
            stp = (stp == 2) ? 0 : stp + 1;
        }
        const float4* sa4 = Sm4 + st * 1024;
        const float4* sb4 = Sm4 + 3072 + st * 1024;
        st = (st == 2) ? 0 : st + 1;
        #pragma unroll
        for (int j = 0; j < 2; j++) {
            int jo = (j == 0) ? jo0 : jo1;   // phys chunk c4+4j for every thread
            float4 bf[4];
            #pragma unroll
            for (int nt = 0; nt < 4; nt++)
                bf[nt] = sb4[bOff[nt] + jo];
            #pragma unroll
            for (int mt = 0; mt < 4; mt++) {
                float4 lo = sa4[aOffL[mt] + jo];
                float4 hi = sa4[aOffH[mt] + jo];
                #pragma unroll
                for (int nt = 0; nt < 4; nt++) {
                    mma_tf32(acc[mt][nt][0], acc[mt][nt][1], acc[mt][nt][2], acc[mt][nt][3],
                             fu(lo.x), fu(hi.x), fu(lo.y), fu(hi.y),
                             fu(bf[nt].x), fu(bf[nt].y));
                    mma_tf32(acc[mt][nt][0], acc[mt][nt][1], acc[mt][nt][2], acc[mt][nt][3],
                             fu(lo.z), fu(hi.z), fu(lo.w), fu(hi.w),
                             fu(bf[nt].z), fu(bf[nt].w));
                }
            }
        }
        __syncthreads();
    }

    int mrow = m0 + wm * 64, ncol = n0 + wn * 32;
    if (mode == 1) {
        int mat = ncol >> 10;
        int dbase = ncol & 1023;
        const float* bias = (mat == 0) ? bias0 : (mat == 1) ? bias1 : bias2;
        float* C = (mat == 0) ? C0 : (mat == 1) ? C1 : C2;
        if (mat == 2) {
            // V: transposed scatter -> [bh][dim][L]
            #pragma unroll
            for (int mt = 0; mt < 4; mt++) {
                int row0 = mrow + mt * 16 + r;           // l index
                int bidx = row0 >> 11, l = row0 & (L_ - 1);
                #pragma unroll
                for (int nt = 0; nt < 4; nt++) {
                    int dcol = dbase + nt * 8 + 2 * c4;
                    int head = dcol >> 6, hd = dcol & 63;
                    float b0 = bias[dcol], b1 = bias[dcol + 1];
                    float* dT = C + ((size_t)(bidx * H_ + head) * HD_ + hd) * L_ + l;
                    dT[0]      = tf32r(acc[mt][nt][0] + b0);
                    dT[L_]     = tf32r(acc[mt][nt][1] + b1);
                    dT[8]      = tf32r(acc[mt][nt][2] + b0);
                    dT[L_ + 8] = tf32r(acc[mt][nt][3] + b1);
                }
            }
        } else {
            #pragma unroll
            for (int mt = 0; mt < 4; mt++) {
                int row0 = mrow + mt * 16 + r;
                int bidx = row0 >> 11, l = row0 & (L_ - 1);
                #pragma unroll
                for (int nt = 0; nt < 4; nt++) {
                    int dcol = dbase + nt * 8 + 2 * c4;
                    int head = dcol >> 6, hd = dcol & 63;
                    float b0 = bias[dcol], b1 = bias[dcol + 1];
                    float* d0 = C + ((size_t)(bidx * H_ + head) * L_ + l) * HD_ + hd;
                    float* d1 = C + ((size_t)(bidx * H_ + head) * L_ + l + 8) * HD_ + hd;
                    float2 v0 = {tf32r(acc[mt][nt][0] + b0), tf32r(acc[mt][nt][1] + b1)};
                    float2 v1 = {tf32r(acc[mt][nt][2] + b0), tf32r(acc[mt][nt][3] + b1)};
                    *(float2*)d0 = v0;
                    *(float2*)d1 = v1;
                }
            }
        }
    } else {
        #pragma unroll
        for (int mt = 0; mt < 4; mt++) {
            int row0 = mrow + mt * 16 + r;
            #pragma unroll
            for (int nt = 0; nt < 4; nt++) {
                int col = ncol + nt * 8 + 2 * c4;
                float b0 = bias0[col], b1 = bias0[col + 1];
                float2 r0 = *(const float2*)(res + (size_t)row0 * D_ + col);
                float2 r1 = *(const float2*)(res + (size_t)(row0 + 8) * D_ + col);
                float2 v0 = {acc[mt][nt][0] + b0 + r0.x, acc[mt][nt][1] + b1 + r0.y};
                float2 v1 = {acc[mt][nt][2] + b0 + r1.x, acc[mt][nt][3] + b1 + r1.y};
                *(float2*)(C0 + (size_t)row0 * D_ + col) = v0;
                *(float2*)(C0 + (size_t)(row0 + 8) * D_ + col) = v1;
            }
        }
    }
}

// ---------------- tf32 TC flash attention ----------------
// CTA: 64 query rows, 4 warps x 16 rows, K-tile 64, double-buffered.
// K chunk-swizzled, read with parity-reordered offsets (uniform phys chunks).
// Q fragments plain phys order. V TRANSPOSED -> dim-major smem; PV fully
// vectorized (no swizzle on P/V -> inherently uniform). 2 CTAs/SM.
#define PSTRF 68
__global__ __launch_bounds__(128, 2) void attn_tc_kernel(
    const float* __restrict__ Q, const float* __restrict__ K,
    const float* __restrict__ V, float* __restrict__ O) {
    extern __shared__ float4 smf4[];
    float4* Ks4 = smf4;                   // [2][64*16] chunk-swizzled
    float4* Vs4 = smf4 + 2048;            // [2][64*17] dim-major, stride 17 f4
    float*  Ps  = (float*)(smf4 + 2048 + 2176);  // [4][16][68]
    int t = threadIdx.x, w = t >> 5, lane = t & 31;
    int r = lane >> 2, c4 = lane & 3;
    int rp = r & 1;
    int qt = gridDim.x - 1 - blockIdx.x;
    int bh = blockIdx.y;
    int bidx = bh >> 4, head = bh & (H_ - 1);
    int len = g_len[bidx];
    int gqw = qt * 64 + w * 16;

    // Q fragments, plain physical order: qa[2p+s2] <-> dims 16p+4c4+2s2{,+1}
    const float* Qb = Q + ((size_t)bh * L_ + gqw) * HD_;
    uint32_t qa[8][4];
    #pragma unroll
    for (int p = 0; p < 4; p++)
        #pragma unroll
        for (int s2 = 0; s2 < 2; s2++) {
            int d0 = 16 * p + 4 * c4 + 2 * s2;
            float2 lo = *(const float2*)(Qb + r * 64 + d0);
            float2 hi = *(const float2*)(Qb + (r + 8) * 64 + d0);
            qa[2 * p + s2][0] = fu(lo.x * 0.125f);
            qa[2 * p + s2][1] = fu(hi.x * 0.125f);
            qa[2 * p + s2][2] = fu(lo.y * 0.125f);
            qa[2 * p + s2][3] = fu(hi.y * 0.125f);
        }

    // parity-reordered chunk offsets for K reads: kj[j] = 4*((j&1)^rp) + 8*(j>>1)
    int kj0 = rp * 4, kj1 = 4 - rp * 4, kj2 = 8 + rp * 4, kj3 = 12 - rp * 4;

    // loop-invariant read offsets (float4 units), base includes c4
    int kOff[8], vOff[8];
    #pragma unroll
    for (int nt = 0; nt < 8; nt++) {
        kOff[nt] = (nt * 8 + r) * 16 + c4;
        vOff[nt] = (nt * 8 + r) * 17 + c4;
    }
    int pOffL = r * 17 + c4, pOffH = (r + 8) * 17 + c4;

    float o_[8][4] = {};
    float m0v = -1e30f, m1v = -1e30f, l0 = 0.f, l1 = 0.f;
    float* pwf = Ps + w * 1088;
    const float4* pw4 = (const float4*)pwf;
    int nkt = qt + 1;

    auto load_stage = [&](int stg, int kt2) {
        const float* Kb = K + ((size_t)bh * L_ + kt2 * 64) * HD_;
        const float* Vb = V + (size_t)bh * HD_ * L_ + kt2 * 64;   // [dim][L]
        float4* sk = Ks4 + stg * 1024;
        float4* sv = Vs4 + stg * 1088;
        #pragma unroll
        for (int i = 0; i < 8; i++) {
            int cid = t + i * 128;
            int row = cid >> 4, cc = cid & 15;
            uint32_t dst = (uint32_t)__cvta_generic_to_shared(
                sk + row * 16 + (cc ^ ((row & 1) * 4)));
            CPA16(dst, Kb + row * 64 + cc * 4);
        }
        #pragma unroll
        for (int i = 0; i < 8; i++) {
            int cid = t + i * 128;
            int row = cid >> 4, cc = cid & 15;    // row = dim, cc*4 = key
            uint32_t dst = (uint32_t)__cvta_generic_to_shared(sv + row * 17 + cc);
            CPA16(dst, Vb + (size_t)row * L_ + cc * 4);
        }
    };

    load_stage(0, 0);
    CPA_COMMIT;
    #pragma unroll 1
    for (int kt = 0; kt < nkt; kt++) {
        if (kt + 1 < nkt) {
            load_stage((kt + 1) & 1, kt + 1);
            CPA_COMMIT;
            asm volatile("cp.async.wait_group 1;\n");
        } else {
            asm volatile("cp.async.wait_group 0;\n");
        }
        __syncthreads();
        int kbase = kt * 64;
        if (kbase <= gqw + 15 && kbase < len) {
            const float4* ks4 = Ks4 + (kt & 1) * 1024;
            const float4* vs4 = Vs4 + (kt & 1) * 1088;
            // ---- S = Q K^T (uniform phys chunk c4+4j) ----
            float s[8][4] = {};
            #pragma unroll
            for (int j = 0; j < 4; j++) {
                int jo = (j == 0) ? kj0 : (j == 1) ? kj1 : (j == 2) ? kj2 : kj3;
                #pragma unroll
                for (int nt = 0; nt < 8; nt++) {
                    float4 kb = ks4[kOff[nt] + jo];
                    mma_tf32(s[nt][0], s[nt][1], s[nt][2], s[nt][3],
                             qa[2 * j][0], qa[2 * j][1], qa[2 * j][2], qa[2 * j][3],
                             fu(kb.x), fu(kb.y));
                    mma_tf32(s[nt][0], s[nt][1], s[nt][2], s[nt][3],
                             qa[2 * j + 1][0], qa[2 * j + 1][1], qa[2 * j + 1][2], qa[2 * j + 1][3],
                             fu(kb.z), fu(kb.w));
                }
            }
            // ---- masking (length + causal) ----
            int gq0 = gqw + r, gq1 = gq0 + 8;
            bool full = (kbase + 63 <= gqw) && (kbase + 64 <= len);
            if (!full) {
                #pragma unroll
                for (int nt = 0; nt < 8; nt++) {
                    int kc = kbase + nt * 8 + 2 * c4;
                    if (!(kc     <= gq0 && kc     < len)) s[nt][0] = -1e30f;
                    if (!(kc + 1 <= gq0 && kc + 1 < len)) s[nt][1] = -1e30f;
                    if (!(kc     <= gq1 && kc     < len)) s[nt][2] = -1e30f;
                    if (!(kc + 1 <= gq1 && kc + 1 < len)) s[nt][3] = -1e30f;
                }
            }
            // ---- online softmax ----
            float mx0 = -1e30f, mx1 = -1e30f;
            #pragma unroll
            for (int nt = 0; nt < 8; nt++) {
                mx0 = fmaxf(mx0, fmaxf(s[nt][0], s[nt][1]));
                mx1 = fmaxf(mx1, fmaxf(s[nt][2], s[nt][3]));
            }
            mx0 = fmaxf(mx0, __shfl_xor_sync(0xffffffffu, mx0, 1));
            mx0 = fmaxf(mx0, __shfl_xor_sync(0xffffffffu, mx0, 2));
            mx1 = fmaxf(mx1, __shfl_xor_sync(0xffffffffu, mx1, 1));
            mx1 = fmaxf(mx1, __shfl_xor_sync(0xffffffffu, mx1, 2));
            float nm0 = fmaxf(m0v, mx0), nm1 = fmaxf(m1v, mx1);
            float sc0 = __expf(m0v - nm0), sc1 = __expf(m1v - nm1);
            m0v = nm0; m1v = nm1;
            float rs0 = 0.f, rs1 = 0.f;
            #pragma unroll
            for (int nt = 0; nt < 8; nt++) {
                s[nt][0] = __expf(s[nt][0] - nm0); rs0 += s[nt][0];
                s[nt][1] = __expf(s[nt][1] - nm0); rs0 += s[nt][1];
                s[nt][2] = __expf(s[nt][2] - nm1); rs1 += s[nt][2];
                s[nt][3] = __expf(s[nt][3] - nm1); rs1 += s[nt][3];
            }
            rs0 += __shfl_xor_sync(0xffffffffu, rs0, 1);
            rs0 += __shfl_xor_sync(0xffffffffu, rs0, 2);
            rs1 += __shfl_xor_sync(0xffffffffu, rs1, 1);
            rs1 += __shfl_xor_sync(0xffffffffu, rs1, 2);
            l0 = l0 * sc0 + rs0;
            l1 = l1 * sc1 + rs1;
            #pragma unroll
            for (int nt = 0; nt < 8; nt++) {
                o_[nt][0] *= sc0; o_[nt][1] *= sc0;
                o_[nt][2] *= sc1; o_[nt][3] *= sc1;
                float2 p0 = {tf32r(s[nt][0]), tf32r(s[nt][1])};
                float2 p1 = {tf32r(s[nt][2]), tf32r(s[nt][3])};
                *(float2*)(pwf + r * PSTRF + nt * 8 + 2 * c4) = p0;
                *(float2*)(pwf + (r + 8) * PSTRF + nt * 8 + 2 * c4) = p1;
            }
            __syncwarp();
            // ---- O += P V (vectorized; no swizzle on P/V -> uniform slots) ----
            #pragma unroll
            for (int p = 0; p < 4; p++) {
                float4 lo = pw4[pOffL + p * 4];
                float4 hi = pw4[pOffH + p * 4];
                #pragma unroll
                for (int nt = 0; nt < 8; nt++) {
                    float4 vb = vs4[vOff[nt] + p * 4];
                    mma_tf32(o_[nt][0], o_[nt][1], o_[nt][2], o_[nt][3],
                             fu(lo.x), fu(hi.x), fu(lo.y), fu(hi.y),
                             fu(vb.x), fu(vb.y));
                    mma_tf32(o_[nt][0], o_[nt][1], o_[nt][2], o_[nt][3],
                             fu(lo.z), fu(hi.z), fu(lo.w), fu(hi.w),
                             fu(vb.z), fu(vb.w));
                }
            }
            __syncwarp();
        }
        __syncthreads();
    }

    float inv0 = 1.0f / l0, inv1 = 1.0f / l1;
    size_t ob = (size_t)bidx * L_ + gqw;
    #pragma unroll
    for (int nt = 0; nt < 8; nt++) {
        int col = head * HD_ + nt * 8 + 2 * c4;
        float2 v0 = {tf32r(o_[nt][0] * inv0), tf32r(o_[nt][1] * inv0)};
        float2 v1 = {tf32r(o_[nt][2] * inv1), tf32r(o_[nt][3] * inv1)};
        *(float2*)(O + (ob + r) * D_ + col) = v0;
        *(float2*)(O + (ob + r + 8) * D_ + col) = v1;
    }
}

// ---------------- launch ----------------
extern "C" void kernel_launch(void* const* d_in, const int* in_sizes, int n_in,
                              void* d_out, int out_size) {
    const float* x     = (const float*)d_in[0];
    const void*  pmask = d_in[1];
    const float* Wq = (const float*)d_in[3];
    const float* bq = (const float*)d_in[4];
    const float* Wk = (const float*)d_in[5];
    const float* bk = (const float*)d_in[6];
    const float* Wv = (const float*)d_in[7];
    const float* bv = (const float*)d_in[8];
    const float* Wo = (const float*)d_in[9];
    const float* bo = (const float*)d_in[10];
    const float* g_pre = (const float*)d_in[11];
    const float* b_pre = (const float*)d_in[12];
    const float* g_ln  = (const float*)d_in[13];
    const float* b_ln  = (const float*)d_in[14];
    float* out = (float*)d_out;

    float *h, *q, *k, *v, *att, *y, *wqkv, *wo4;
    cudaGetSymbolAddress((void**)&h,    g_h);
    cudaGetSymbolAddress((void**)&q,    g_q);
    cudaGetSymbolAddress((void**)&k,    g_k);
    cudaGetSymbolAddress((void**)&v,    g_v);
    cudaGetSymbolAddress((void**)&att,  g_att);
    cudaGetSymbolAddress((void**)&y,    g_y);
    cudaGetSymbolAddress((void**)&wqkv, g_wqkv);
    cudaGetSymbolAddress((void**)&wo4,  g_wo4);

    const int gemm_smem = 6 * 1024 * 16;                       // 98304
    const int attn_smem = (2048 + 2176) * 16 + 4 * 1088 * 4;   // 84992
    cudaFuncSetAttribute(tgemm_kernel,   cudaFuncAttributeMaxDynamicSharedMemorySize, gemm_smem);
    cudaFuncSetAttribute(attn_tc_kernel, cudaFuncAttributeMaxDynamicSharedMemorySize, attn_smem);

    mask_len_kernel<<<1, 256>>>((const unsigned int*)pmask);
    wround_kernel<<<(D_ * D_) / 256, 256>>>(Wq, Wk, Wv, Wo);
    ln_kernel<<<M_, 256>>>(x, g_pre, b_pre, h, 1);

    // fused QKV projection: N = 3072 (V scattered transposed)
    tgemm_kernel<<<dim3(3 * D_ / 128, M_ / 128), 256, gemm_smem>>>(
        h, wqkv, bq, bk, bv, nullptr, q, k, v, 1);

    attn_tc_kernel<<<dim3(L_ / 64, B_ * H_), 128, attn_smem>>>(q, k, v, att);

    // output projection + residual
    tgemm_kernel<<<dim3(D_ / 128, M_ / 128), 256, gemm_smem>>>(
        att, wo4, bo, bo, bo, h, y, y, y, 0);

    ln_kernel<<<M_, 256>>>(y, g_ln, b_ln, out, 0);
}

// round 12
// speedup vs baseline: 1.0957x; 1.0957x over previous
#include <cuda_runtime.h>
#include <cstdint>

#define B_ 4
#define L_ 2048
#define D_ 1024
#define H_ 16
#define HD_ 64
#define M_ 8192

// ---------------- scratch ----------------
__device__ float g_h[M_ * D_];
__device__ float g_q[M_ * D_];
__device__ float g_k[M_ * D_];
__device__ float g_v[M_ * D_];       // V stored TRANSPOSED: [bh][dim][L]
__device__ float g_att[M_ * D_];
__device__ float g_y[M_ * D_];
__device__ float g_wqkv[3 * D_ * D_];
__device__ float g_wo4[D_ * D_];
__device__ int   g_len[B_];

// ---------------- helpers ----------------
__device__ __forceinline__ float tf32r(float x) {
    float y; asm("cvt.rna.tf32.f32 %0, %1;" : "=f"(y) : "f"(x)); return y;
}
__device__ __forceinline__ uint32_t fu(float x) { return __float_as_uint(x); }
#define CPA16(dst, src) asm volatile("cp.async.cg.shared.global [%0], [%1], 16;\n" ::"r"(dst), "l"(src))
#define CPA_COMMIT asm volatile("cp.async.commit_group;\n")

__device__ __forceinline__ void mma_tf32(float& c0, float& c1, float& c2, float& c3,
                                         uint32_t a0, uint32_t a1, uint32_t a2, uint32_t a3,
                                         uint32_t b0, uint32_t b1) {
    asm volatile(
        "mma.sync.aligned.m16n8k8.row.col.f32.tf32.tf32.f32 "
        "{%0,%1,%2,%3}, {%4,%5,%6,%7}, {%8,%9}, {%0,%1,%2,%3};\n"
        : "+f"(c0), "+f"(c1), "+f"(c2), "+f"(c3)
        : "r"(a0), "r"(a1), "r"(a2), "r"(a3), "r"(b0), "r"(b1));
}

// ---------------- mask -> lengths ----------------
__global__ void mask_len_kernel(const unsigned int* __restrict__ pw) {
    __shared__ int s_bad;
    int t = threadIdx.x;
    if (t == 0) s_bad = 0;
    if (t < B_) g_len[t] = L_;
    __syncthreads();
    int bad = 0;
    for (int i = t; i < (B_ * L_) / 4; i += 256) {
        unsigned v = pw[i];
        if (v != 0u && v != 1u && v != 0x3F800000u) bad = 1;
    }
    if (bad) atomicExch(&s_bad, 1);
    __syncthreads();
    if (s_bad) {
        const unsigned char* pb = (const unsigned char*)pw;
        for (int i = t; i < B_ * L_; i += 256)
            if (pb[i]) atomicMin(&g_len[i >> 11], i & (L_ - 1));
    } else {
        for (int i = t; i < B_ * L_; i += 256)
            if (pw[i]) atomicMin(&g_len[i >> 11], i & (L_ - 1));
    }
}

// ---------------- weight tf32 pre-round ----------------
__global__ void wround_kernel(const float* __restrict__ a, const float* __restrict__ b,
                              const float* __restrict__ c, const float* __restrict__ d) {
    int i = blockIdx.x * 256 + threadIdx.x;
    g_wqkv[i]               = tf32r(a[i]);
    g_wqkv[D_ * D_ + i]     = tf32r(b[i]);
    g_wqkv[2 * D_ * D_ + i] = tf32r(c[i]);
    g_wo4[i]                = tf32r(d[i]);
}

// ---------------- LayerNorm ----------------
__global__ void ln_kernel(const float* __restrict__ x, const float* __restrict__ gamma,
                          const float* __restrict__ beta, float* __restrict__ out, int rnd) {
    __shared__ float red[8];
    __shared__ float s_mu, s_rs;
    int row = blockIdx.x;
    int t = threadIdx.x;
    float4 v = ((const float4*)(x + (size_t)row * D_))[t];
    float s = v.x + v.y + v.z + v.w;
    #pragma unroll
    for (int o = 16; o; o >>= 1) s += __shfl_xor_sync(0xffffffffu, s, o);
    if ((t & 31) == 0) red[t >> 5] = s;
    __syncthreads();
    if (t == 0) {
        float tot = 0.f;
        #pragma unroll
        for (int i = 0; i < 8; i++) tot += red[i];
        s_mu = tot * (1.0f / D_);
    }
    __syncthreads();
    float mu = s_mu;
    float dx = v.x - mu, dy = v.y - mu, dz = v.z - mu, dw = v.w - mu;
    float ss = dx * dx + dy * dy + dz * dz + dw * dw;
    #pragma unroll
    for (int o = 16; o; o >>= 1) ss += __shfl_xor_sync(0xffffffffu, ss, o);
    __syncthreads();
    if ((t & 31) == 0) red[t >> 5] = ss;
    __syncthreads();
    if (t == 0) {
        float tot = 0.f;
        #pragma unroll
        for (int i = 0; i < 8; i++) tot += red[i];
        s_rs = rsqrtf(tot * (1.0f / D_) + 1e-5f);
    }
    __syncthreads();
    float rs = s_rs;
    float4 gv = ((const float4*)gamma)[t];
    float4 bv = ((const float4*)beta)[t];
    float4 o4;
    o4.x = dx * rs * gv.x + bv.x;
    o4.y = dy * rs * gv.y + bv.y;
    o4.z = dz * rs * gv.z + bv.z;
    o4.w = dw * rs * gv.w + bv.w;
    if (rnd) { o4.x = tf32r(o4.x); o4.y = tf32r(o4.y); o4.z = tf32r(o4.z); o4.w = tf32r(o4.w); }
    ((float4*)(out + (size_t)row * D_))[t] = o4;
}

// ---------------- tf32 TC GEMM: C = A(MxK) x W(NxK)^T + bias ----------------
// Block 128x128, 8 warps of 64x32, BK=32, 3-stage cp.async with pointer-
// increment loading (no per-iter address rebuild). Store-side chunk swizzle;
// reads use parity-reordered offsets (uniform phys chunks -> correct pairing,
// proven in R11). 2 CTAs/SM.
#define BK_ 32
#define NK_ (D_ / BK_)
__global__ __launch_bounds__(256, 2) void tgemm_kernel(
    const float* __restrict__ A, const float* __restrict__ W,
    const float* __restrict__ bias0, const float* __restrict__ bias1,
    const float* __restrict__ bias2, const float* __restrict__ res,
    float* __restrict__ C0, float* __restrict__ C1, float* __restrict__ C2,
    int mode) {
    extern __shared__ float4 Sm4[];     // [3][1024] A | [3][1024] B (B at +3072)
    int t = threadIdx.x, w = t >> 5, lane = t & 31;
    int r = lane >> 2, c4 = lane & 3;
    int rp = r & 1;
    int m0 = blockIdx.y * 128, n0 = blockIdx.x * 128;
    int wm = w >> 2, wn = w & 3;

    float acc[4][4][4] = {};

    int jo0 = rp * 4, jo1 = 4 - rp * 4;

    // loop-invariant read offsets (float4 units)
    int aOffL[4], aOffH[4], bOff[4];
    #pragma unroll
    for (int mt = 0; mt < 4; mt++) {
        aOffL[mt] = (wm * 64 + mt * 16 + r) * 8 + c4;
        aOffH[mt] = aOffL[mt] + 64;
    }
    #pragma unroll
    for (int nt = 0; nt < 4; nt++)
        bOff[nt] = (wn * 32 + nt * 8 + r) * 8 + c4;

    // ---- pointer-increment staging state ----
    int lrow = t >> 3;                   // 0..31
    int lcc  = t & 7;
    int ccsw = lcc ^ ((lrow & 1) * 4);   // row parity fixed across j (rows +32)
    uint32_t dstA0 = (uint32_t)__cvta_generic_to_shared(Sm4) + (lrow * 8 + ccsw) * 16;
    uint32_t dstB0 = dstA0 + 3072 * 16;
    const float* pA = A + (size_t)(m0 + lrow) * D_ + lcc * 4;
    const float* pB = W + (size_t)(n0 + lrow) * D_ + lcc * 4;

    auto load_stage = [&](int st) {
        uint32_t sA = dstA0 + st * 16384;
        uint32_t sB = dstB0 + st * 16384;
        #pragma unroll
        for (int j = 0; j < 4; j++) {
            CPA16(sA + j * 4096, pA + (size_t)j * 32 * D_);
            CPA16(sB + j * 4096, pB + (size_t)j * 32 * D_);
        }
        pA += BK_; pB += BK_;
    };

    load_stage(0);
    CPA_COMMIT;
    load_stage(1);
    CPA_COMMIT;

    int st = 0, stp = 2;
    #pragma unroll 1
    for (int kb = 0; kb < NK_; kb++) {
        if (kb + 1 < NK_) asm volatile("cp.async.wait_group 1;\n");
        else              asm volatile("cp.async.wait_group 0;\n");
        __syncthreads();
        if (kb + 2 < NK_) {
            load_stage(stp);
            CPA_COMMIT;
            stp = (stp == 2) ? 0 : stp + 1;
        }
        const float4* sa4 = Sm4 + st * 1024;
        const float4* sb4 = Sm4 + 3072 + st * 1024;
        st = (st == 2) ? 0 : st + 1;
        #pragma unroll
        for (int j = 0; j < 2; j++) {
            int jo = (j == 0) ? jo0 : jo1;   // phys chunk c4+4j for every thread
            float4 bf[4];
            #pragma unroll
            for (int nt = 0; nt < 4; nt++)
                bf[nt] = sb4[bOff[nt] + jo];
            #pragma unroll
            for (int mt = 0; mt < 4; mt++) {
                float4 lo = sa4[aOffL[mt] + jo];
                float4 hi = sa4[aOffH[mt] + jo];
                #pragma unroll
                for (int nt = 0; nt < 4; nt++) {
                    mma_tf32(acc[mt][nt][0], acc[mt][nt][1], acc[mt][nt][2], acc[mt][nt][3],
                             fu(lo.x), fu(hi.x), fu(lo.y), fu(hi.y),
                             fu(bf[nt].x), fu(bf[nt].y));
                    mma_tf32(acc[mt][nt][0], acc[mt][nt][1], acc[mt][nt][2], acc[mt][nt][3],
                             fu(lo.z), fu(hi.z), fu(lo.w), fu(hi.w),
                             fu(bf[nt].z), fu(bf[nt].w));
                }
            }
        }
        __syncthreads();
    }

    int mrow = m0 + wm * 64, ncol = n0 + wn * 32;
    if (mode == 1) {
        int mat = ncol >> 10;
        int dbase = ncol & 1023;
        const float* bias = (mat == 0) ? bias0 : (mat == 1) ? bias1 : bias2;
        float* C = (mat == 0) ? C0 : (mat == 1) ? C1 : C2;
        if (mat == 2) {
            // V: transposed scatter -> [bh][dim][L]
            #pragma unroll
            for (int mt = 0; mt < 4; mt++) {
                int row0 = mrow + mt * 16 + r;           // l index
                int bidx = row0 >> 11, l = row0 & (L_ - 1);
                #pragma unroll
                for (int nt = 0; nt < 4; nt++) {
                    int dcol = dbase + nt * 8 + 2 * c4;
                    int head = dcol >> 6, hd = dcol & 63;
                    float b0 = bias[dcol], b1 = bias[dcol + 1];
                    float* dT = C + ((size_t)(bidx * H_ + head) * HD_ + hd) * L_ + l;
                    dT[0]      = tf32r(acc[mt][nt][0] + b0);
                    dT[L_]     = tf32r(acc[mt][nt][1] + b1);
                    dT[8]      = tf32r(acc[mt][nt][2] + b0);
                    dT[L_ + 8] = tf32r(acc[mt][nt][3] + b1);
                }
            }
        } else {
            #pragma unroll
            for (int mt = 0; mt < 4; mt++) {
                int row0 = mrow + mt * 16 + r;
                int bidx = row0 >> 11, l = row0 & (L_ - 1);
                #pragma unroll
                for (int nt = 0; nt < 4; nt++) {
                    int dcol = dbase + nt * 8 + 2 * c4;
                    int head = dcol >> 6, hd = dcol & 63;
                    float b0 = bias[dcol], b1 = bias[dcol + 1];
                    float* d0 = C + ((size_t)(bidx * H_ + head) * L_ + l) * HD_ + hd;
                    float* d1 = C + ((size_t)(bidx * H_ + head) * L_ + l + 8) * HD_ + hd;
                    float2 v0 = {tf32r(acc[mt][nt][0] + b0), tf32r(acc[mt][nt][1] + b1)};
                    float2 v1 = {tf32r(acc[mt][nt][2] + b0), tf32r(acc[mt][nt][3] + b1)};
                    *(float2*)d0 = v0;
                    *(float2*)d1 = v1;
                }
            }
        }
    } else {
        #pragma unroll
        for (int mt = 0; mt < 4; mt++) {
            int row0 = mrow + mt * 16 + r;
            #pragma unroll
            for (int nt = 0; nt < 4; nt++) {
                int col = ncol + nt * 8 + 2 * c4;
                float b0 = bias0[col], b1 = bias0[col + 1];
                float2 r0 = *(const float2*)(res + (size_t)row0 * D_ + col);
                float2 r1 = *(const float2*)(res + (size_t)(row0 + 8) * D_ + col);
                float2 v0 = {acc[mt][nt][0] + b0 + r0.x, acc[mt][nt][1] + b1 + r0.y};
                float2 v1 = {acc[mt][nt][2] + b0 + r1.x, acc[mt][nt][3] + b1 + r1.y};
                *(float2*)(C0 + (size_t)row0 * D_ + col) = v0;
                *(float2*)(C0 + (size_t)(row0 + 8) * D_ + col) = v1;
            }
        }
    }
}

// ---------------- tf32 TC flash attention ----------------
// CTA: 64 query rows, 4 warps x 16 rows, K-tile 64, double-buffered,
// pointer-increment staging. K chunk-swizzled (parity-reordered reads).
// V transposed -> dim-major smem stride 20 f4; P stride 20 f4 -> PV fragment
// LDS.128 reads are CONFLICT-FREE (20r+c4 = 4r+c4 mod 8, all distinct).
// 2 CTAs/SM.
#define VST4 20   // V/P row stride in float4 units
__global__ __launch_bounds__(128, 2) void attn_tc_kernel(
    const float* __restrict__ Q, const float* __restrict__ K,
    const float* __restrict__ V, float* __restrict__ O) {
    extern __shared__ float4 smf4[];
    float4* Ks4 = smf4;                   // [2][64*16] chunk-swizzled
    float4* Vs4 = smf4 + 2048;            // [2][64*20] dim-major
    float*  Ps  = (float*)(smf4 + 2048 + 2560);  // [4][16][80]
    int t = threadIdx.x, w = t >> 5, lane = t & 31;
    int r = lane >> 2, c4 = lane & 3;
    int rp = r & 1;
    int qt = gridDim.x - 1 - blockIdx.x;
    int bh = blockIdx.y;
    int bidx = bh >> 4, head = bh & (H_ - 1);
    int len = g_len[bidx];
    int gqw = qt * 64 + w * 16;

    // Q fragments (float4 global loads; slots c4 <-> dims 16p+4c4+{0,1,2,3})
    const float* Qb = Q + ((size_t)bh * L_ + gqw) * HD_;
    uint32_t qa[8][4];
    #pragma unroll
    for (int p = 0; p < 4; p++) {
        float4 lo4 = *(const float4*)(Qb + r * 64 + 16 * p + 4 * c4);
        float4 hi4 = *(const float4*)(Qb + (r + 8) * 64 + 16 * p + 4 * c4);
        qa[2 * p][0]     = fu(lo4.x * 0.125f);
        qa[2 * p][1]     = fu(hi4.x * 0.125f);
        qa[2 * p][2]     = fu(lo4.y * 0.125f);
        qa[2 * p][3]     = fu(hi4.y * 0.125f);
        qa[2 * p + 1][0] = fu(lo4.z * 0.125f);
        qa[2 * p + 1][1] = fu(hi4.z * 0.125f);
        qa[2 * p + 1][2] = fu(lo4.w * 0.125f);
        qa[2 * p + 1][3] = fu(hi4.w * 0.125f);
    }

    // parity-reordered chunk offsets for K reads (uniform phys chunk c4+4j)
    int kj0 = rp * 4, kj1 = 4 - rp * 4, kj2 = 8 + rp * 4, kj3 = 12 - rp * 4;

    // loop-invariant read offsets (float4 units)
    int kOff[8], vOff[8];
    #pragma unroll
    for (int nt = 0; nt < 8; nt++) {
        kOff[nt] = (nt * 8 + r) * 16 + c4;
        vOff[nt] = (nt * 8 + r) * VST4 + c4;
    }
    int pOffL = r * VST4 + c4, pOffH = (r + 8) * VST4 + c4;

    float o_[8][4] = {};
    float m0v = -1e30f, m1v = -1e30f, l0 = 0.f, l1 = 0.f;
    float* pwf = Ps + w * (16 * VST4 * 4);       // 16 rows x 80 floats per warp
    const float4* pw4 = (const float4*)pwf;
    int nkt = qt + 1;

    // ---- pointer-increment staging state ----
    int vrow = t >> 4;                    // 0..7
    int vcc  = t & 15;
    int ksw  = vcc ^ ((vrow & 1) * 4);    // row parity fixed across i (rows +8)
    uint32_t dstK0 = (uint32_t)__cvta_generic_to_shared(Ks4) + (vrow * 16 + ksw) * 16;
    uint32_t dstV0 = (uint32_t)__cvta_generic_to_shared(Vs4) + (vrow * VST4 + vcc) * 16;
    const float* pK = K + (size_t)bh * L_ * HD_ + vrow * 64 + vcc * 4;
    const float* pV = V + (size_t)bh * HD_ * L_ + (size_t)vrow * L_ + vcc * 4;

    auto load_stage = [&](int stg) {
        uint32_t sK = dstK0 + stg * 16384;          // 1024 f4 per stage
        uint32_t sV = dstV0 + stg * (1280 * 16);    // 1280 f4 per stage
        #pragma unroll
        for (int i = 0; i < 8; i++)
            CPA16(sK + i * 2048, pK + i * 512);             // +8 rows
        #pragma unroll
        for (int i = 0; i < 8; i++)
            CPA16(sV + i * (8 * VST4 * 16), pV + (size_t)i * 8 * L_);
        pK += 64 * HD_;
        pV += 64;
    };

    load_stage(0);
    CPA_COMMIT;
    #pragma unroll 1
    for (int kt = 0; kt < nkt; kt++) {
        if (kt + 1 < nkt) {
            load_stage((kt + 1) & 1);
            CPA_COMMIT;
            asm volatile("cp.async.wait_group 1;\n");
        } else {
            asm volatile("cp.async.wait_group 0;\n");
        }
        __syncthreads();
        int kbase = kt * 64;
        if (kbase <= gqw + 15 && kbase < len) {
            const float4* ks4 = Ks4 + (kt & 1) * 1024;
            const float4* vs4 = Vs4 + (kt & 1) * 1280;
            // ---- S = Q K^T ----
            float s[8][4] = {};
            #pragma unroll
            for (int j = 0; j < 4; j++) {
                int jo = (j == 0) ? kj0 : (j == 1) ? kj1 : (j == 2) ? kj2 : kj3;
                #pragma unroll
                for (int nt = 0; nt < 8; nt++) {
                    float4 kb = ks4[kOff[nt] + jo];
                    mma_tf32(s[nt][0], s[nt][1], s[nt][2], s[nt][3],
                             qa[2 * j][0], qa[2 * j][1], qa[2 * j][2], qa[2 * j][3],
                             fu(kb.x), fu(kb.y));
                    mma_tf32(s[nt][0], s[nt][1], s[nt][2], s[nt][3],
                             qa[2 * j + 1][0], qa[2 * j + 1][1], qa[2 * j + 1][2], qa[2 * j + 1][3],
                             fu(kb.z), fu(kb.w));
                }
            }
            // ---- masking (length + causal) ----
            int gq0 = gqw + r, gq1 = gq0 + 8;
            bool full = (kbase + 63 <= gqw) && (kbase + 64 <= len);
            if (!full) {
                #pragma unroll
                for (int nt = 0; nt < 8; nt++) {
                    int kc = kbase + nt * 8 + 2 * c4;
                    if (!(kc     <= gq0 && kc     < len)) s[nt][0] = -1e30f;
                    if (!(kc + 1 <= gq0 && kc + 1 < len)) s[nt][1] = -1e30f;
                    if (!(kc     <= gq1 && kc     < len)) s[nt][2] = -1e30f;
                    if (!(kc + 1 <= gq1 && kc + 1 < len)) s[nt][3] = -1e30f;
                }
            }
            // ---- online softmax ----
            float mx0 = -1e30f, mx1 = -1e30f;
            #pragma unroll
            for (int nt = 0; nt < 8; nt++) {
                mx0 = fmaxf(mx0, fmaxf(s[nt][0], s[nt][1]));
                mx1 = fmaxf(mx1, fmaxf(s[nt][2], s[nt][3]));
            }
            mx0 = fmaxf(mx0, __shfl_xor_sync(0xffffffffu, mx0, 1));
            mx0 = fmaxf(mx0, __shfl_xor_sync(0xffffffffu, mx0, 2));
            mx1 = fmaxf(mx1, __shfl_xor_sync(0xffffffffu, mx1, 1));
            mx1 = fmaxf(mx1, __shfl_xor_sync(0xffffffffu, mx1, 2));
            float nm0 = fmaxf(m0v, mx0), nm1 = fmaxf(m1v, mx1);
            float sc0 = __expf(m0v - nm0), sc1 = __expf(m1v - nm1);
            m0v = nm0; m1v = nm1;
            float rs0 = 0.f, rs1 = 0.f;
            #pragma unroll
            for (int nt = 0; nt < 8; nt++) {
                s[nt][0] = __expf(s[nt][0] - nm0); rs0 += s[nt][0];
                s[nt][1] = __expf(s[nt][1] - nm0); rs0 += s[nt][1];
                s[nt][2] = __expf(s[nt][2] - nm1); rs1 += s[nt][2];
                s[nt][3] = __expf(s[nt][3] - nm1); rs1 += s[nt][3];
            }
            rs0 += __shfl_xor_sync(0xffffffffu, rs0, 1);
            rs0 += __shfl_xor_sync(0xffffffffu, rs0, 2);
            rs1 += __shfl_xor_sync(0xffffffffu, rs1, 1);
            rs1 += __shfl_xor_sync(0xffffffffu, rs1, 2);
            l0 = l0 * sc0 + rs0;
            l1 = l1 * sc1 + rs1;
            #pragma unroll
            for (int nt = 0; nt < 8; nt++) {
                o_[nt][0] *= sc0; o_[nt][1] *= sc0;
                o_[nt][2] *= sc1; o_[nt][3] *= sc1;
                float2 p0 = {tf32r(s[nt][0]), tf32r(s[nt][1])};
                float2 p1 = {tf32r(s[nt][2]), tf32r(s[nt][3])};
                *(float2*)(pwf + r * (VST4 * 4) + nt * 8 + 2 * c4) = p0;
                *(float2*)(pwf + (r + 8) * (VST4 * 4) + nt * 8 + 2 * c4) = p1;
            }
            __syncwarp();
            // ---- O += P V (vectorized, conflict-free stride 20) ----
            #pragma unroll
            for (int p = 0; p < 4; p++) {
                float4 lo = pw4[pOffL + p * 4];
                float4 hi = pw4[pOffH + p * 4];
                #pragma unroll
                for (int nt = 0; nt < 8; nt++) {
                    float4 vb = vs4[vOff[nt] + p * 4];
                    mma_tf32(o_[nt][0], o_[nt][1], o_[nt][2], o_[nt][3],
                             fu(lo.x), fu(hi.x), fu(lo.y), fu(hi.y),
                             fu(vb.x), fu(vb.y));
                    mma_tf32(o_[nt][0], o_[nt][1], o_[nt][2], o_[nt][3],
                             fu(lo.z), fu(hi.z), fu(lo.w), fu(hi.w),
                             fu(vb.z), fu(vb.w));
                }
            }
            __syncwarp();
        }
        __syncthreads();
    }

    float inv0 = 1.0f / l0, inv1 = 1.0f / l1;
    size_t ob = (size_t)bidx * L_ + gqw;
    #pragma unroll
    for (int nt = 0; nt < 8; nt++) {
        int col = head * HD_ + nt * 8 + 2 * c4;
        float2 v0 = {tf32r(o_[nt][0] * inv0), tf32r(o_[nt][1] * inv0)};
        float2 v1 = {tf32r(o_[nt][2] * inv1), tf32r(o_[nt][3] * inv1)};
        *(float2*)(O + (ob + r) * D_ + col) = v0;
        *(float2*)(O + (ob + r + 8) * D_ + col) = v1;
    }
}

// ---------------- launch ----------------
extern "C" void kernel_launch(void* const* d_in, const int* in_sizes, int n_in,
                              void* d_out, int out_size) {
    const float* x     = (const float*)d_in[0];
    const void*  pmask = d_in[1];
    const float* Wq = (const float*)d_in[3];
    const float* bq = (const float*)d_in[4];
    const float* Wk = (const float*)d_in[5];
    const float* bk = (const float*)d_in[6];
    const float* Wv = (const float*)d_in[7];
    const float* bv = (const float*)d_in[8];
    const float* Wo = (const float*)d_in[9];
    const float* bo = (const float*)d_in[10];
    const float* g_pre = (const float*)d_in[11];
    const float* b_pre = (const float*)d_in[12];
    const float* g_ln  = (const float*)d_in[13];
    const float* b_ln  = (const float*)d_in[14];
    float* out = (float*)d_out;

    float *h, *q, *k, *v, *att, *y, *wqkv, *wo4;
    cudaGetSymbolAddress((void**)&h,    g_h);
    cudaGetSymbolAddress((void**)&q,    g_q);
    cudaGetSymbolAddress((void**)&k,    g_k);
    cudaGetSymbolAddress((void**)&v,    g_v);
    cudaGetSymbolAddress((void**)&att,  g_att);
    cudaGetSymbolAddress((void**)&y,    g_y);
    cudaGetSymbolAddress((void**)&wqkv, g_wqkv);
    cudaGetSymbolAddress((void**)&wo4,  g_wo4);

    const int gemm_smem = 6 * 1024 * 16;                         // 98304
    const int attn_smem = (2048 + 2560 + 4 * 320) * 16;          // 94208
    cudaFuncSetAttribute(tgemm_kernel,   cudaFuncAttributeMaxDynamicSharedMemorySize, gemm_smem);
    cudaFuncSetAttribute(attn_tc_kernel, cudaFuncAttributeMaxDynamicSharedMemorySize, attn_smem);

    mask_len_kernel<<<1, 256>>>((const unsigned int*)pmask);
    wround_kernel<<<(D_ * D_) / 256, 256>>>(Wq, Wk, Wv, Wo);
    ln_kernel<<<M_, 256>>>(x, g_pre, b_pre, h, 1);

    // fused QKV projection: N = 3072 (V scattered transposed)
    tgemm_kernel<<<dim3(3 * D_ / 128, M_ / 128), 256, gemm_smem>>>(
        h, wqkv, bq, bk, bv, nullptr, q, k, v, 1);

    attn_tc_kernel<<<dim3(L_ / 64, B_ * H_), 128, attn_smem>>>(q, k, v, att);

    // output projection + residual
    tgemm_kernel<<<dim3(D_ / 128, M_ / 128), 256, gemm_smem>>>(
        att, wo4, bo, bo, bo, h, y, y, y, 0);

    ln_kernel<<<M_, 256>>>(y, g_ln, b_ln, out, 0);
}

// round 14
// speedup vs baseline: 1.1001x; 1.0040x over previous
#include <cuda_runtime.h>
#include <cstdint>

#define B_ 4
#define L_ 2048
#define D_ 1024
#define H_ 16
#define HD_ 64
#define M_ 8192

// ---------------- scratch ----------------
__device__ float g_h[M_ * D_];
__device__ float g_q[M_ * D_];
__device__ float g_k[M_ * D_];
__device__ float g_v[M_ * D_];       // V stored TRANSPOSED: [bh][dim][L]
__device__ float g_att[M_ * D_];
__device__ float g_y[M_ * D_];
__device__ float g_wqkv[3 * D_ * D_];
__device__ float g_wo4[D_ * D_];
__device__ int   g_len[B_];

// ---------------- helpers ----------------
__device__ __forceinline__ float tf32r(float x) {
    float y; asm("cvt.rna.tf32.f32 %0, %1;" : "=f"(y) : "f"(x)); return y;
}
__device__ __forceinline__ uint32_t fu(float x) { return __float_as_uint(x); }
#define CPA16(dst, src) asm volatile("cp.async.cg.shared.global [%0], [%1], 16;\n" ::"r"(dst), "l"(src))
#define CPA_COMMIT asm volatile("cp.async.commit_group;\n")

__device__ __forceinline__ void mma_tf32(float& c0, float& c1, float& c2, float& c3,
                                         uint32_t a0, uint32_t a1, uint32_t a2, uint32_t a3,
                                         uint32_t b0, uint32_t b1) {
    asm volatile(
        "mma.sync.aligned.m16n8k8.row.col.f32.tf32.tf32.f32 "
        "{%0,%1,%2,%3}, {%4,%5,%6,%7}, {%8,%9}, {%0,%1,%2,%3};\n"
        : "+f"(c0), "+f"(c1), "+f"(c2), "+f"(c3)
        : "r"(a0), "r"(a1), "r"(a2), "r"(a3), "r"(b0), "r"(b1));
}

// ---------------- mask -> lengths ----------------
__global__ void mask_len_kernel(const unsigned int* __restrict__ pw) {
    __shared__ int s_bad;
    int t = threadIdx.x;
    if (t == 0) s_bad = 0;
    if (t < B_) g_len[t] = L_;
    __syncthreads();
    int bad = 0;
    for (int i = t; i < (B_ * L_) / 4; i += 256) {
        unsigned v = pw[i];
        if (v != 0u && v != 1u && v != 0x3F800000u) bad = 1;
    }
    if (bad) atomicExch(&s_bad, 1);
    __syncthreads();
    if (s_bad) {
        const unsigned char* pb = (const unsigned char*)pw;
        for (int i = t; i < B_ * L_; i += 256)
            if (pb[i]) atomicMin(&g_len[i >> 11], i & (L_ - 1));
    } else {
        for (int i = t; i < B_ * L_; i += 256)
            if (pw[i]) atomicMin(&g_len[i >> 11], i & (L_ - 1));
    }
}

// ---------------- weight tf32 pre-round ----------------
__global__ void wround_kernel(const float* __restrict__ a, const float* __restrict__ b,
                              const float* __restrict__ c, const float* __restrict__ d) {
    int i = blockIdx.x * 256 + threadIdx.x;
    g_wqkv[i]               = tf32r(a[i]);
    g_wqkv[D_ * D_ + i]     = tf32r(b[i]);
    g_wqkv[2 * D_ * D_ + i] = tf32r(c[i]);
    g_wo4[i]                = tf32r(d[i]);
}

// ---------------- LayerNorm: one WARP per row (no block barriers) ----------------
__global__ void ln_kernel(const float* __restrict__ x, const float* __restrict__ gamma,
                          const float* __restrict__ beta, float* __restrict__ out, int rnd) {
    int row  = (blockIdx.x * blockDim.x + threadIdx.x) >> 5;
    int lane = threadIdx.x & 31;
    const float4* xr = (const float4*)(x + (size_t)row * D_);
    float4 v[8];
    float s = 0.f;
    #pragma unroll
    for (int i = 0; i < 8; i++) {
        v[i] = xr[lane + i * 32];
        s += v[i].x + v[i].y + v[i].z + v[i].w;
    }
    #pragma unroll
    for (int o = 16; o; o >>= 1) s += __shfl_xor_sync(0xffffffffu, s, o);
    float mu = s * (1.0f / D_);
    float ss = 0.f;
    #pragma unroll
    for (int i = 0; i < 8; i++) {
        v[i].x -= mu; v[i].y -= mu; v[i].z -= mu; v[i].w -= mu;
        ss += v[i].x * v[i].x + v[i].y * v[i].y + v[i].z * v[i].z + v[i].w * v[i].w;
    }
    #pragma unroll
    for (int o = 16; o; o >>= 1) ss += __shfl_xor_sync(0xffffffffu, ss, o);
    float rs = rsqrtf(ss * (1.0f / D_) + 1e-5f);
    const float4* g4 = (const float4*)gamma;
    const float4* b4 = (const float4*)beta;
    float4* o4 = (float4*)(out + (size_t)row * D_);
    #pragma unroll
    for (int i = 0; i < 8; i++) {
        float4 gv = g4[lane + i * 32];
        float4 bv = b4[lane + i * 32];
        float4 o;
        o.x = v[i].x * rs * gv.x + bv.x;
        o.y = v[i].y * rs * gv.y + bv.y;
        o.z = v[i].z * rs * gv.z + bv.z;
        o.w = v[i].w * rs * gv.w + bv.w;
        if (rnd) { o.x = tf32r(o.x); o.y = tf32r(o.y); o.z = tf32r(o.z); o.w = tf32r(o.w); }
        o4[lane + i * 32] = o;
    }
}

// ---------------- tf32 TC GEMM: C = A(MxK) x W(NxK)^T + bias ----------------
// Block 128x128, 8 warps of 64x32, BK=32, 3-stage cp.async, pointer-increment
// staging, parity-reordered reads. SINGLE syncthreads per iteration (3-stage
// ring: write target was last read 2 iters ago; top barrier covers it).
// 2 CTAs/SM.
#define BK_ 32
#define NK_ (D_ / BK_)
__global__ __launch_bounds__(256, 2) void tgemm_kernel(
    const float* __restrict__ A, const float* __restrict__ W,
    const float* __restrict__ bias0, const float* __restrict__ bias1,
    const float* __restrict__ bias2, const float* __restrict__ res,
    float* __restrict__ C0, float* __restrict__ C1, float* __restrict__ C2,
    int mode) {
    extern __shared__ float4 Sm4[];     // [3][1024] A | [3][1024] B (B at +3072)
    int t = threadIdx.x, w = t >> 5, lane = t & 31;
    int r = lane >> 2, c4 = lane & 3;
    int rp = r & 1;
    int m0 = blockIdx.y * 128, n0 = blockIdx.x * 128;
    int wm = w >> 2, wn = w & 3;

    float acc[4][4][4] = {};

    int jo0 = rp * 4, jo1 = 4 - rp * 4;

    int aOffL[4], aOffH[4], bOff[4];
    #pragma unroll
    for (int mt = 0; mt < 4; mt++) {
        aOffL[mt] = (wm * 64 + mt * 16 + r) * 8 + c4;
        aOffH[mt] = aOffL[mt] + 64;
    }
    #pragma unroll
    for (int nt = 0; nt < 4; nt++)
        bOff[nt] = (wn * 32 + nt * 8 + r) * 8 + c4;

    // ---- pointer-increment staging state ----
    int lrow = t >> 3;                   // 0..31
    int lcc  = t & 7;
    int ccsw = lcc ^ ((lrow & 1) * 4);
    uint32_t dstA0 = (uint32_t)__cvta_generic_to_shared(Sm4) + (lrow * 8 + ccsw) * 16;
    uint32_t dstB0 = dstA0 + 3072 * 16;
    const float* pA = A + (size_t)(m0 + lrow) * D_ + lcc * 4;
    const float* pB = W + (size_t)(n0 + lrow) * D_ + lcc * 4;

    auto load_stage = [&](int st) {
        uint32_t sA = dstA0 + st * 16384;
        uint32_t sB = dstB0 + st * 16384;
        #pragma unroll
        for (int j = 0; j < 4; j++) {
            CPA16(sA + j * 4096, pA + (size_t)j * 32 * D_);
            CPA16(sB + j * 4096, pB + (size_t)j * 32 * D_);
        }
        pA += BK_; pB += BK_;
    };

    load_stage(0);
    CPA_COMMIT;
    load_stage(1);
    CPA_COMMIT;

    int st = 0, stp = 2;
    #pragma unroll 1
    for (int kb = 0; kb < NK_; kb++) {
        if (kb + 1 < NK_) asm volatile("cp.async.wait_group 1;\n");
        else              asm volatile("cp.async.wait_group 0;\n");
        __syncthreads();
        if (kb + 2 < NK_) {
            load_stage(stp);
            CPA_COMMIT;
            stp = (stp == 2) ? 0 : stp + 1;
        }
        const float4* sa4 = Sm4 + st * 1024;
        const float4* sb4 = Sm4 + 3072 + st * 1024;
        st = (st == 2) ? 0 : st + 1;
        #pragma unroll
        for (int j = 0; j < 2; j++) {
            int jo = (j == 0) ? jo0 : jo1;   // phys chunk c4+4j for every thread
            float4 bf[4];
            #pragma unroll
            for (int nt = 0; nt < 4; nt++)
                bf[nt] = sb4[bOff[nt] + jo];
            #pragma unroll
            for (int mt = 0; mt < 4; mt++) {
                float4 lo = sa4[aOffL[mt] + jo];
                float4 hi = sa4[aOffH[mt] + jo];
                #pragma unroll
                for (int nt = 0; nt < 4; nt++) {
                    mma_tf32(acc[mt][nt][0], acc[mt][nt][1], acc[mt][nt][2], acc[mt][nt][3],
                             fu(lo.x), fu(hi.x), fu(lo.y), fu(hi.y),
                             fu(bf[nt].x), fu(bf[nt].y));
                    mma_tf32(acc[mt][nt][0], acc[mt][nt][1], acc[mt][nt][2], acc[mt][nt][3],
                             fu(lo.z), fu(hi.z), fu(lo.w), fu(hi.w),
                             fu(bf[nt].z), fu(bf[nt].w));
                }
            }
        }
        // no trailing syncthreads: 3-stage ring + top barrier cover the hazard
    }

    int mrow = m0 + wm * 64, ncol = n0 + wn * 32;
    if (mode == 1) {
        int mat = ncol >> 10;
        int dbase = ncol & 1023;
        const float* bias = (mat == 0) ? bias0 : (mat == 1) ? bias1 : bias2;
        float* C = (mat == 0) ? C0 : (mat == 1) ? C1 : C2;
        if (mat == 2) {
            // V: transposed scatter -> [bh][dim][L]
            #pragma unroll
            for (int mt = 0; mt < 4; mt++) {
                int row0 = mrow + mt * 16 + r;           // l index
                int bidx = row0 >> 11, l = row0 & (L_ - 1);
                #pragma unroll
                for (int nt = 0; nt < 4; nt++) {
                    int dcol = dbase + nt * 8 + 2 * c4;
                    int head = dcol >> 6, hd = dcol & 63;
                    float b0 = bias[dcol], b1 = bias[dcol + 1];
                    float* dT = C + ((size_t)(bidx * H_ + head) * HD_ + hd) * L_ + l;
                    dT[0]      = tf32r(acc[mt][nt][0] + b0);
                    dT[L_]     = tf32r(acc[mt][nt][1] + b1);
                    dT[8]      = tf32r(acc[mt][nt][2] + b0);
                    dT[L_ + 8] = tf32r(acc[mt][nt][3] + b1);
                }
            }
        } else {
            #pragma unroll
            for (int mt = 0; mt < 4; mt++) {
                int row0 = mrow + mt * 16 + r;
                int bidx = row0 >> 11, l = row0 & (L_ - 1);
                #pragma unroll
                for (int nt = 0; nt < 4; nt++) {
                    int dcol = dbase + nt * 8 + 2 * c4;
                    int head = dcol >> 6, hd = dcol & 63;
                    float b0 = bias[dcol], b1 = bias[dcol + 1];
                    float* d0 = C + ((size_t)(bidx * H_ + head) * L_ + l) * HD_ + hd;
                    float* d1 = C + ((size_t)(bidx * H_ + head) * L_ + l + 8) * HD_ + hd;
                    float2 v0 = {tf32r(acc[mt][nt][0] + b0), tf32r(acc[mt][nt][1] + b1)};
                    float2 v1 = {tf32r(acc[mt][nt][2] + b0), tf32r(acc[mt][nt][3] + b1)};
                    *(float2*)d0 = v0;
                    *(float2*)d1 = v1;
                }
            }
        }
    } else {
        #pragma unroll
        for (int mt = 0; mt < 4; mt++) {
            int row0 = mrow + mt * 16 + r;
            #pragma unroll
            for (int nt = 0; nt < 4; nt++) {
                int col = ncol + nt * 8 + 2 * c4;
                float b0 = bias0[col], b1 = bias0[col + 1];
                float2 r0 = *(const float2*)(res + (size_t)row0 * D_ + col);
                float2 r1 = *(const float2*)(res + (size_t)(row0 + 8) * D_ + col);
                float2 v0 = {acc[mt][nt][0] + b0 + r0.x, acc[mt][nt][1] + b1 + r0.y};
                float2 v1 = {acc[mt][nt][2] + b0 + r1.x, acc[mt][nt][3] + b1 + r1.y};
                *(float2*)(C0 + (size_t)row0 * D_ + col) = v0;
                *(float2*)(C0 + (size_t)(row0 + 8) * D_ + col) = v1;
            }
        }
    }
}

// ---------------- tf32 TC flash attention ----------------
// CTA: 64 query rows, 4 warps x 16 rows, K-tile 64, double-buffered,
// pointer-increment staging. Loads issued AFTER the barrier -> single
// syncthreads per K-tile (wait_group 0 since newest group is the needed one).
// K chunk-swizzled (parity-reordered reads); V transposed, stride 20 f4;
// P stride 20 f4 (conflict-free LDS.128). 2 CTAs/SM.
#define VST4 20   // V/P row stride in float4 units
__global__ __launch_bounds__(128, 2) void attn_tc_kernel(
    const float* __restrict__ Q, const float* __restrict__ K,
    const float* __restrict__ V, float* __restrict__ O) {
    extern __shared__ float4 smf4[];
    float4* Ks4 = smf4;                   // [2][64*16] chunk-swizzled
    float4* Vs4 = smf4 + 2048;            // [2][64*20] dim-major
    float*  Ps  = (float*)(smf4 + 2048 + 2560);  // [4][16][80]
    int t = threadIdx.x, w = t >> 5, lane = t & 31;
    int r = lane >> 2, c4 = lane & 3;
    int rp = r & 1;
    int qt = gridDim.x - 1 - blockIdx.x;
    int bh = blockIdx.y;
    int bidx = bh >> 4, head = bh & (H_ - 1);
    int len = g_len[bidx];
    int gqw = qt * 64 + w * 16;

    // Q fragments (float4 global loads; slots c4 <-> dims 16p+4c4+{0,1,2,3})
    const float* Qb = Q + ((size_t)bh * L_ + gqw) * HD_;
    uint32_t qa[8][4];
    #pragma unroll
    for (int p = 0; p < 4; p++) {
        float4 lo4 = *(const float4*)(Qb + r * 64 + 16 * p + 4 * c4);
        float4 hi4 = *(const float4*)(Qb + (r + 8) * 64 + 16 * p + 4 * c4);
        qa[2 * p][0]     = fu(lo4.x * 0.125f);
        qa[2 * p][1]     = fu(hi4.x * 0.125f);
        qa[2 * p][2]     = fu(lo4.y * 0.125f);
        qa[2 * p][3]     = fu(hi4.y * 0.125f);
        qa[2 * p + 1][0] = fu(lo4.z * 0.125f);
        qa[2 * p + 1][1] = fu(hi4.z * 0.125f);
        qa[2 * p + 1][2] = fu(lo4.w * 0.125f);
        qa[2 * p + 1][3] = fu(hi4.w * 0.125f);
    }

    // parity-reordered chunk offsets for K reads (uniform phys chunk c4+4j)
    int kj0 = rp * 4, kj1 = 4 - rp * 4, kj2 = 8 + rp * 4, kj3 = 12 - rp * 4;

    int kOff[8], vOff[8];
    #pragma unroll
    for (int nt = 0; nt < 8; nt++) {
        kOff[nt] = (nt * 8 + r) * 16 + c4;
        vOff[nt] = (nt * 8 + r) * VST4 + c4;
    }
    int pOffL = r * VST4 + c4, pOffH = (r + 8) * VST4 + c4;

    float o_[8][4] = {};
    float m0v = -1e30f, m1v = -1e30f, l0 = 0.f, l1 = 0.f;
    float* pwf = Ps + w * (16 * VST4 * 4);
    const float4* pw4 = (const float4*)pwf;
    int nkt = qt + 1;

    // ---- pointer-increment staging state ----
    int vrow = t >> 4;                    // 0..7
    int vcc  = t & 15;
    int ksw  = vcc ^ ((vrow & 1) * 4);
    uint32_t dstK0 = (uint32_t)__cvta_generic_to_shared(Ks4) + (vrow * 16 + ksw) * 16;
    uint32_t dstV0 = (uint32_t)__cvta_generic_to_shared(Vs4) + (vrow * VST4 + vcc) * 16;
    const float* pK = K + (size_t)bh * L_ * HD_ + vrow * 64 + vcc * 4;
    const float* pV = V + (size_t)bh * HD_ * L_ + (size_t)vrow * L_ + vcc * 4;

    auto load_stage = [&](int stg) {
        uint32_t sK = dstK0 + stg * 16384;          // 1024 f4 per stage
        uint32_t sV = dstV0 + stg * (1280 * 16);    // 1280 f4 per stage
        #pragma unroll
        for (int i = 0; i < 8; i++)
            CPA16(sK + i * 2048, pK + i * 512);             // +8 rows
        #pragma unroll
        for (int i = 0; i < 8; i++)
            CPA16(sV + i * (8 * VST4 * 16), pV + (size_t)i * 8 * L_);
        pK += 64 * HD_;
        pV += 64;
    };

    load_stage(0);
    CPA_COMMIT;
    #pragma unroll 1
    for (int kt = 0; kt < nkt; kt++) {
        asm volatile("cp.async.wait_group 0;\n");
        __syncthreads();
        if (kt + 1 < nkt) {
            load_stage((kt + 1) & 1);
            CPA_COMMIT;
        }
        int kbase = kt * 64;
        if (kbase <= gqw + 15 && kbase < len) {
            const float4* ks4 = Ks4 + (kt & 1) * 1024;
            const float4* vs4 = Vs4 + (kt & 1) * 1280;
            // ---- S = Q K^T ----
            float s[8][4] = {};
            #pragma unroll
            for (int j = 0; j < 4; j++) {
                int jo = (j == 0) ? kj0 : (j == 1) ? kj1 : (j == 2) ? kj2 : kj3;
                #pragma unroll
                for (int nt = 0; nt < 8; nt++) {
                    float4 kb = ks4[kOff[nt] + jo];
                    mma_tf32(s[nt][0], s[nt][1], s[nt][2], s[nt][3],
                             qa[2 * j][0], qa[2 * j][1], qa[2 * j][2], qa[2 * j][3],
                             fu(kb.x), fu(kb.y));
                    mma_tf32(s[nt][0], s[nt][1], s[nt][2], s[nt][3],
                             qa[2 * j + 1][0], qa[2 * j + 1][1], qa[2 * j + 1][2], qa[2 * j + 1][3],
                             fu(kb.z), fu(kb.w));
                }
            }
            // ---- masking (length + causal) ----
            int gq0 = gqw + r, gq1 = gq0 + 8;
            bool full = (kbase + 63 <= gqw) && (kbase + 64 <= len);
            if (!full) {
                #pragma unroll
                for (int nt = 0; nt < 8; nt++) {
                    int kc = kbase + nt * 8 + 2 * c4;
                    if (!(kc     <= gq0 && kc     < len)) s[nt][0] = -1e30f;
                    if (!(kc + 1 <= gq0 && kc + 1 < len)) s[nt][1] = -1e30f;
                    if (!(kc     <= gq1 && kc     < len)) s[nt][2] = -1e30f;
                    if (!(kc + 1 <= gq1 && kc + 1 < len)) s[nt][3] = -1e30f;
                }
            }
            // ---- online softmax ----
            float mx0 = -1e30f, mx1 = -1e30f;
            #pragma unroll
            for (int nt = 0; nt < 8; nt++) {
                mx0 = fmaxf(mx0, fmaxf(s[nt][0], s[nt][1]));
                mx1 = fmaxf(mx1, fmaxf(s[nt][2], s[nt][3]));
            }
            mx0 = fmaxf(mx0, __shfl_xor_sync(0xffffffffu, mx0, 1));
            mx0 = fmaxf(mx0, __shfl_xor_sync(0xffffffffu, mx0, 2));
            mx1 = fmaxf(mx1, __shfl_xor_sync(0xffffffffu, mx1, 1));
            mx1 = fmaxf(mx1, __shfl_xor_sync(0xffffffffu, mx1, 2));
            float nm0 = fmaxf(m0v, mx0), nm1 = fmaxf(m1v, mx1);
            float sc0 = __expf(m0v - nm0), sc1 = __expf(m1v - nm1);
            m0v = nm0; m1v = nm1;
            float rs0 = 0.f, rs1 = 0.f;
            #pragma unroll
            for (int nt = 0; nt < 8; nt++) {
                s[nt][0] = __expf(s[nt][0] - nm0); rs0 += s[nt][0];
                s[nt][1] = __expf(s[nt][1] - nm0); rs0 += s[nt][1];
                s[nt][2] = __expf(s[nt][2] - nm1); rs1 += s[nt][2];
                s[nt][3] = __expf(s[nt][3] - nm1); rs1 += s[nt][3];
            }
            rs0 += __shfl_xor_sync(0xffffffffu, rs0, 1);
            rs0 += __shfl_xor_sync(0xffffffffu, rs0, 2);
            rs1 += __shfl_xor_sync(0xffffffffu, rs1, 1);
            rs1 += __shfl_xor_sync(0xffffffffu, rs1, 2);
            l0 = l0 * sc0 + rs0;
            l1 = l1 * sc1 + rs1;
            #pragma unroll
            for (int nt = 0; nt < 8; nt++) {
                o_[nt][0] *= sc0; o_[nt][1] *= sc0;
                o_[nt][2] *= sc1; o_[nt][3] *= sc1;
                float2 p0 = {tf32r(s[nt][0]), tf32r(s[nt][1])};
                float2 p1 = {tf32r(s[nt][2]), tf32r(s[nt][3])};
                *(float2*)(pwf + r * (VST4 * 4) + nt * 8 + 2 * c4) = p0;
                *(float2*)(pwf + (r + 8) * (VST4 * 4) + nt * 8 + 2 * c4) = p1;
            }
            __syncwarp();
            // ---- O += P V (vectorized, conflict-free stride 20) ----
            #pragma unroll
            for (int p = 0; p < 4; p++) {
                float4 lo = pw4[pOffL + p * 4];
                float4 hi = pw4[pOffH + p * 4];
                #pragma unroll
                for (int nt = 0; nt < 8; nt++) {
                    float4 vb = vs4[vOff[nt] + p * 4];
                    mma_tf32(o_[nt][0], o_[nt][1], o_[nt][2], o_[nt][3],
                             fu(lo.x), fu(hi.x), fu(lo.y), fu(hi.y),
                             fu(vb.x), fu(vb.y));
                    mma_tf32(o_[nt][0], o_[nt][1], o_[nt][2], o_[nt][3],
                             fu(lo.z), fu(hi.z), fu(lo.w), fu(hi.w),
                             fu(vb.z), fu(vb.w));
                }
            }
            __syncwarp();
        }
        // no trailing syncthreads: loads for stage (kt+1)&1 are issued only
        // after the NEXT top barrier, which orders them after this compute
    }

    float inv0 = 1.0f / l0, inv1 = 1.0f / l1;
    size_t ob = (size_t)bidx * L_ + gqw;
    #pragma unroll
    for (int nt = 0; nt < 8; nt++) {
        int col = head * HD_ + nt * 8 + 2 * c4;
        float2 v0 = {tf32r(o_[nt][0] * inv0), tf32r(o_[nt][1] * inv0)};
        float2 v1 = {tf32r(o_[nt][2] * inv1), tf32r(o_[nt][3] * inv1)};
        *(float2*)(O + (ob + r) * D_ + col) = v0;
        *(float2*)(O + (ob + r + 8) * D_ + col) = v1;
    }
}

// ---------------- launch ----------------
extern "C" void kernel_launch(void* const* d_in, const int* in_sizes, int n_in,
                              void* d_out, int out_size) {
    const float* x     = (const float*)d_in[0];
    const void*  pmask = d_in[1];
    const float* Wq = (const float*)d_in[3];
    const float* bq = (const float*)d_in[4];
    const float* Wk = (const float*)d_in[5];
    const float* bk = (const float*)d_in[6];
    const float* Wv = (const float*)d_in[7];
    const float* bv = (const float*)d_in[8];
    const float* Wo = (const float*)d_in[9];
    const float* bo = (const float*)d_in[10];
    const float* g_pre = (const float*)d_in[11];
    const float* b_pre = (const float*)d_in[12];
    const float* g_ln  = (const float*)d_in[13];
    const float* b_ln  = (const float*)d_in[14];
    float* out = (float*)d_out;

    float *h, *q, *k, *v, *att, *y, *wqkv, *wo4;
    cudaGetSymbolAddress((void**)&h,    g_h);
    cudaGetSymbolAddress((void**)&q,    g_q);
    cudaGetSymbolAddress((void**)&k,    g_k);
    cudaGetSymbolAddress((void**)&v,    g_v);
    cudaGetSymbolAddress((void**)&att,  g_att);
    cudaGetSymbolAddress((void**)&y,    g_y);
    cudaGetSymbolAddress((void**)&wqkv, g_wqkv);
    cudaGetSymbolAddress((void**)&wo4,  g_wo4);

    const int gemm_smem = 6 * 1024 * 16;                         // 98304
    const int attn_smem = (2048 + 2560 + 4 * 320) * 16;          // 94208
    cudaFuncSetAttribute(tgemm_kernel,   cudaFuncAttributeMaxDynamicSharedMemorySize, gemm_smem);
    cudaFuncSetAttribute(attn_tc_kernel, cudaFuncAttributeMaxDynamicSharedMemorySize, attn_smem);

    mask_len_kernel<<<1, 256>>>((const unsigned int*)pmask);
    wround_kernel<<<(D_ * D_) / 256, 256>>>(Wq, Wk, Wv, Wo);
    ln_kernel<<<M_ / 8, 256>>>(x, g_pre, b_pre, h, 1);

    // fused QKV projection: N = 3072 (V scattered transposed)
    tgemm_kernel<<<dim3(3 * D_ / 128, M_ / 128), 256, gemm_smem>>>(
        h, wqkv, bq, bk, bv, nullptr, q, k, v, 1);

    attn_tc_kernel<<<dim3(L_ / 64, B_ * H_), 128, attn_smem>>>(q, k, v, att);

    // output projection + residual
    tgemm_kernel<<<dim3(D_ / 128, M_ / 128), 256, gemm_smem>>>(
        att, wo4, bo, bo, bo, h, y, y, y, 0);

    ln_kernel<<<M_ / 8, 256>>>(y, g_ln, b_ln, out, 0);
}

// round 16
// speedup vs baseline: 1.2864x; 1.1693x over previous
#include <cuda_runtime.h>
#include <cuda_bf16.h>
#include <cstdint>

#define B_ 4
#define L_ 2048
#define D_ 1024
#define H_ 16
#define HD_ 64
#define M_ 8192
#define LOG2E_ 1.44269504088896340736f

// ---------------- scratch ----------------
__device__ float g_h[M_ * D_];
__device__ float g_q[M_ * D_];
__device__ float g_k[M_ * D_];
__device__ __nv_bfloat16 g_v[M_ * D_];   // V TRANSPOSED bf16: [bh][dim][L]
__device__ float g_att[M_ * D_];
__device__ float g_y[M_ * D_];
__device__ float g_wqkv[3 * D_ * D_];
__device__ float g_wo4[D_ * D_];
__device__ int   g_len[B_];

// ---------------- helpers ----------------
__device__ __forceinline__ float tf32r(float x) {
    float y; asm("cvt.rna.tf32.f32 %0, %1;" : "=f"(y) : "f"(x)); return y;
}
__device__ __forceinline__ uint32_t fu(float x) { return __float_as_uint(x); }
__device__ __forceinline__ float ex2f(float x) {
    float y; asm("ex2.approx.f32 %0, %1;" : "=f"(y) : "f"(x)); return y;
}
// pack {lo, hi} floats -> bf16x2 register (lo in low half)
__device__ __forceinline__ uint32_t packbf(float lo, float hi) {
    uint32_t d;
    asm("cvt.rn.bf16x2.f32 %0, %1, %2;" : "=r"(d) : "f"(hi), "f"(lo));
    return d;
}
#define CPA16(dst, src) asm volatile("cp.async.cg.shared.global [%0], [%1], 16;\n" ::"r"(dst), "l"(src))
#define CPA_COMMIT asm volatile("cp.async.commit_group;\n")

__device__ __forceinline__ void mma_tf32(float& c0, float& c1, float& c2, float& c3,
                                         uint32_t a0, uint32_t a1, uint32_t a2, uint32_t a3,
                                         uint32_t b0, uint32_t b1) {
    asm volatile(
        "mma.sync.aligned.m16n8k8.row.col.f32.tf32.tf32.f32 "
        "{%0,%1,%2,%3}, {%4,%5,%6,%7}, {%8,%9}, {%0,%1,%2,%3};\n"
        : "+f"(c0), "+f"(c1), "+f"(c2), "+f"(c3)
        : "r"(a0), "r"(a1), "r"(a2), "r"(a3), "r"(b0), "r"(b1));
}
__device__ __forceinline__ void mma_bf16(float& c0, float& c1, float& c2, float& c3,
                                         uint32_t a0, uint32_t a1, uint32_t a2, uint32_t a3,
                                         uint32_t b0, uint32_t b1) {
    asm volatile(
        "mma.sync.aligned.m16n8k16.row.col.f32.bf16.bf16.f32 "
        "{%0,%1,%2,%3}, {%4,%5,%6,%7}, {%8,%9}, {%0,%1,%2,%3};\n"
        : "+f"(c0), "+f"(c1), "+f"(c2), "+f"(c3)
        : "r"(a0), "r"(a1), "r"(a2), "r"(a3), "r"(b0), "r"(b1));
}

// ---------------- mask -> lengths ----------------
__global__ void mask_len_kernel(const unsigned int* __restrict__ pw) {
    __shared__ int s_bad;
    int t = threadIdx.x;
    if (t == 0) s_bad = 0;
    if (t < B_) g_len[t] = L_;
    __syncthreads();
    int bad = 0;
    for (int i = t; i < (B_ * L_) / 4; i += 256) {
        unsigned v = pw[i];
        if (v != 0u && v != 1u && v != 0x3F800000u) bad = 1;
    }
    if (bad) atomicExch(&s_bad, 1);
    __syncthreads();
    if (s_bad) {
        const unsigned char* pb = (const unsigned char*)pw;
        for (int i = t; i < B_ * L_; i += 256)
            if (pb[i]) atomicMin(&g_len[i >> 11], i & (L_ - 1));
    } else {
        for (int i = t; i < B_ * L_; i += 256)
            if (pw[i]) atomicMin(&g_len[i >> 11], i & (L_ - 1));
    }
}

// ---------------- weight tf32 pre-round ----------------
__global__ void wround_kernel(const float* __restrict__ a, const float* __restrict__ b,
                              const float* __restrict__ c, const float* __restrict__ d) {
    int i = blockIdx.x * 256 + threadIdx.x;
    g_wqkv[i]               = tf32r(a[i]);
    g_wqkv[D_ * D_ + i]     = tf32r(b[i]);
    g_wqkv[2 * D_ * D_ + i] = tf32r(c[i]);
    g_wo4[i]                = tf32r(d[i]);
}

// ---------------- LayerNorm: one WARP per row ----------------
__global__ void ln_kernel(const float* __restrict__ x, const float* __restrict__ gamma,
                          const float* __restrict__ beta, float* __restrict__ out, int rnd) {
    int row  = (blockIdx.x * blockDim.x + threadIdx.x) >> 5;
    int lane = threadIdx.x & 31;
    const float4* xr = (const float4*)(x + (size_t)row * D_);
    float4 v[8];
    float s = 0.f;
    #pragma unroll
    for (int i = 0; i < 8; i++) {
        v[i] = xr[lane + i * 32];
        s += v[i].x + v[i].y + v[i].z + v[i].w;
    }
    #pragma unroll
    for (int o = 16; o; o >>= 1) s += __shfl_xor_sync(0xffffffffu, s, o);
    float mu = s * (1.0f / D_);
    float ss = 0.f;
    #pragma unroll
    for (int i = 0; i < 8; i++) {
        v[i].x -= mu; v[i].y -= mu; v[i].z -= mu; v[i].w -= mu;
        ss += v[i].x * v[i].x + v[i].y * v[i].y + v[i].z * v[i].z + v[i].w * v[i].w;
    }
    #pragma unroll
    for (int o = 16; o; o >>= 1) ss += __shfl_xor_sync(0xffffffffu, ss, o);
    float rs = rsqrtf(ss * (1.0f / D_) + 1e-5f);
    const float4* g4 = (const float4*)gamma;
    const float4* b4 = (const float4*)beta;
    float4* o4 = (float4*)(out + (size_t)row * D_);
    #pragma unroll
    for (int i = 0; i < 8; i++) {
        float4 gv = g4[lane + i * 32];
        float4 bv = b4[lane + i * 32];
        float4 o;
        o.x = v[i].x * rs * gv.x + bv.x;
        o.y = v[i].y * rs * gv.y + bv.y;
        o.z = v[i].z * rs * gv.z + bv.z;
        o.w = v[i].w * rs * gv.w + bv.w;
        if (rnd) { o.x = tf32r(o.x); o.y = tf32r(o.y); o.z = tf32r(o.z); o.w = tf32r(o.w); }
        o4[lane + i * 32] = o;
    }
}

// ---------------- tf32 TC GEMM: C = A(MxK) x W(NxK)^T + bias ----------------
// R14-proven: 128x128 CTA, 8 warps 64x32, BK=32, 3-stage cp.async ring,
// pointer-increment staging, parity-reordered reads, single barrier/iter.
// mode 1: QKV fused; Q,K -> tf32 heads layout; V -> TRANSPOSED bf16.
// mode 0: row-major + residual.
#define BK_ 32
#define NK_ (D_ / BK_)
__global__ __launch_bounds__(256, 2) void tgemm_kernel(
    const float* __restrict__ A, const float* __restrict__ W,
    const float* __restrict__ bias0, const float* __restrict__ bias1,
    const float* __restrict__ bias2, const float* __restrict__ res,
    float* __restrict__ C0, float* __restrict__ C1,
    __nv_bfloat16* __restrict__ Cv, int mode) {
    extern __shared__ float4 Sm4[];     // [3][1024] A | [3][1024] B (B at +3072)
    int t = threadIdx.x, w = t >> 5, lane = t & 31;
    int r = lane >> 2, c4 = lane & 3;
    int rp = r & 1;
    int m0 = blockIdx.y * 128, n0 = blockIdx.x * 128;
    int wm = w >> 2, wn = w & 3;

    float acc[4][4][4] = {};

    int jo0 = rp * 4, jo1 = 4 - rp * 4;

    int aOffL[4], aOffH[4], bOff[4];
    #pragma unroll
    for (int mt = 0; mt < 4; mt++) {
        aOffL[mt] = (wm * 64 + mt * 16 + r) * 8 + c4;
        aOffH[mt] = aOffL[mt] + 64;
    }
    #pragma unroll
    for (int nt = 0; nt < 4; nt++)
        bOff[nt] = (wn * 32 + nt * 8 + r) * 8 + c4;

    int lrow = t >> 3, lcc = t & 7;
    int ccsw = lcc ^ ((lrow & 1) * 4);
    uint32_t dstA0 = (uint32_t)__cvta_generic_to_shared(Sm4) + (lrow * 8 + ccsw) * 16;
    uint32_t dstB0 = dstA0 + 3072 * 16;
    const float* pA = A + (size_t)(m0 + lrow) * D_ + lcc * 4;
    const float* pB = W + (size_t)(n0 + lrow) * D_ + lcc * 4;

    auto load_stage = [&](int st) {
        uint32_t sA = dstA0 + st * 16384;
        uint32_t sB = dstB0 + st * 16384;
        #pragma unroll
        for (int j = 0; j < 4; j++) {
            CPA16(sA + j * 4096, pA + (size_t)j * 32 * D_);
            CPA16(sB + j * 4096, pB + (size_t)j * 32 * D_);
        }
        pA += BK_; pB += BK_;
    };

    load_stage(0);
    CPA_COMMIT;
    load_stage(1);
    CPA_COMMIT;

    int st = 0, stp = 2;
    #pragma unroll 1
    for (int kb = 0; kb < NK_; kb++) {
        if (kb + 1 < NK_) asm volatile("cp.async.wait_group 1;\n");
        else              asm volatile("cp.async.wait_group 0;\n");
        __syncthreads();
        if (kb + 2 < NK_) {
            load_stage(stp);
            CPA_COMMIT;
            stp = (stp == 2) ? 0 : stp + 1;
        }
        const float4* sa4 = Sm4 + st * 1024;
        const float4* sb4 = Sm4 + 3072 + st * 1024;
        st = (st == 2) ? 0 : st + 1;
        #pragma unroll
        for (int j = 0; j < 2; j++) {
            int jo = (j == 0) ? jo0 : jo1;
            float4 bf[4];
            #pragma unroll
            for (int nt = 0; nt < 4; nt++)
                bf[nt] = sb4[bOff[nt] + jo];
            #pragma unroll
            for (int mt = 0; mt < 4; mt++) {
                float4 lo = sa4[aOffL[mt] + jo];
                float4 hi = sa4[aOffH[mt] + jo];
                #pragma unroll
                for (int nt = 0; nt < 4; nt++) {
                    mma_tf32(acc[mt][nt][0], acc[mt][nt][1], acc[mt][nt][2], acc[mt][nt][3],
                             fu(lo.x), fu(hi.x), fu(lo.y), fu(hi.y),
                             fu(bf[nt].x), fu(bf[nt].y));
                    mma_tf32(acc[mt][nt][0], acc[mt][nt][1], acc[mt][nt][2], acc[mt][nt][3],
                             fu(lo.z), fu(hi.z), fu(lo.w), fu(hi.w),
                             fu(bf[nt].z), fu(bf[nt].w));
                }
            }
        }
    }

    int mrow = m0 + wm * 64, ncol = n0 + wn * 32;
    if (mode == 1) {
        int mat = ncol >> 10;
        int dbase = ncol & 1023;
        const float* bias = (mat == 0) ? bias0 : (mat == 1) ? bias1 : bias2;
        if (mat == 2) {
            // V: transposed bf16 scatter -> [bh][dim][L]
            #pragma unroll
            for (int mt = 0; mt < 4; mt++) {
                int row0 = mrow + mt * 16 + r;           // l index
                int bidx = row0 >> 11, l = row0 & (L_ - 1);
                #pragma unroll
                for (int nt = 0; nt < 4; nt++) {
                    int dcol = dbase + nt * 8 + 2 * c4;
                    int head = dcol >> 6, hd = dcol & 63;
                    float b0 = bias[dcol], b1 = bias[dcol + 1];
                    __nv_bfloat16* dT = Cv + ((size_t)(bidx * H_ + head) * HD_ + hd) * L_ + l;
                    dT[0]      = __float2bfloat16(acc[mt][nt][0] + b0);
                    dT[L_]     = __float2bfloat16(acc[mt][nt][1] + b1);
                    dT[8]      = __float2bfloat16(acc[mt][nt][2] + b0);
                    dT[L_ + 8] = __float2bfloat16(acc[mt][nt][3] + b1);
                }
            }
        } else {
            float* C = (mat == 0) ? C0 : C1;
            #pragma unroll
            for (int mt = 0; mt < 4; mt++) {
                int row0 = mrow + mt * 16 + r;
                int bidx = row0 >> 11, l = row0 & (L_ - 1);
                #pragma unroll
                for (int nt = 0; nt < 4; nt++) {
                    int dcol = dbase + nt * 8 + 2 * c4;
                    int head = dcol >> 6, hd = dcol & 63;
                    float b0 = bias[dcol], b1 = bias[dcol + 1];
                    float* d0 = C + ((size_t)(bidx * H_ + head) * L_ + l) * HD_ + hd;
                    float* d1 = C + ((size_t)(bidx * H_ + head) * L_ + l + 8) * HD_ + hd;
                    float2 v0 = {tf32r(acc[mt][nt][0] + b0), tf32r(acc[mt][nt][1] + b1)};
                    float2 v1 = {tf32r(acc[mt][nt][2] + b0), tf32r(acc[mt][nt][3] + b1)};
                    *(float2*)d0 = v0;
                    *(float2*)d1 = v1;
                }
            }
        }
    } else {
        #pragma unroll
        for (int mt = 0; mt < 4; mt++) {
            int row0 = mrow + mt * 16 + r;
            #pragma unroll
            for (int nt = 0; nt < 4; nt++) {
                int col = ncol + nt * 8 + 2 * c4;
                float b0 = bias0[col], b1 = bias0[col + 1];
                float2 r0 = *(const float2*)(res + (size_t)row0 * D_ + col);
                float2 r1 = *(const float2*)(res + (size_t)(row0 + 8) * D_ + col);
                float2 v0 = {acc[mt][nt][0] + b0 + r0.x, acc[mt][nt][1] + b1 + r0.y};
                float2 v1 = {acc[mt][nt][2] + b0 + r1.x, acc[mt][nt][3] + b1 + r1.y};
                *(float2*)(C0 + (size_t)row0 * D_ + col) = v0;
                *(float2*)(C0 + (size_t)(row0 + 8) * D_ + col) = v1;
            }
        }
    }
}

// ---------------- flash attention: tf32 QK^T + bf16 PV ----------------
// CTA: 64 q-rows, 4 warps x 16 rows, K-tile 64, double-buffered, 3 CTAs/SM.
// S fragments ARE the bf16 m16n8k16 A-fragments (packed bf16x2) -> no P smem.
// Softmax in exp2 domain (log2e folded into Q scale).
// V bf16 [dim][key] smem, row stride 72 bf16 (coeff 36 words -> 4r+c4, no conflicts).
#define VROWB 72
__global__ __launch_bounds__(128, 3) void attn_tc_kernel(
    const float* __restrict__ Q, const float* __restrict__ K,
    const __nv_bfloat16* __restrict__ V, float* __restrict__ O) {
    extern __shared__ float4 smf4[];
    float4* Ks4 = smf4;                                   // [2][1024] f4 (32KB)
    __nv_bfloat16* VsB = (__nv_bfloat16*)(smf4 + 2048);   // [2][64][72] bf16 (18KB)
    int t = threadIdx.x, w = t >> 5, lane = t & 31;
    int r = lane >> 2, c4 = lane & 3;
    int rp = r & 1;
    int qt = gridDim.x - 1 - blockIdx.x;
    int bh = blockIdx.y;
    int bidx = bh >> 4, head = bh & (H_ - 1);
    int len = g_len[bidx];
    int gqw = qt * 64 + w * 16;

    // Q fragments: scale = (1/8)*log2e, tf32-rounded
    const float SCL = 0.125f * LOG2E_;
    const float* Qb = Q + ((size_t)bh * L_ + gqw) * HD_;
    uint32_t qa[8][4];
    #pragma unroll
    for (int p = 0; p < 4; p++) {
        float4 lo4 = *(const float4*)(Qb + r * 64 + 16 * p + 4 * c4);
        float4 hi4 = *(const float4*)(Qb + (r + 8) * 64 + 16 * p + 4 * c4);
        qa[2 * p][0]     = fu(tf32r(lo4.x * SCL));
        qa[2 * p][1]     = fu(tf32r(hi4.x * SCL));
        qa[2 * p][2]     = fu(tf32r(lo4.y * SCL));
        qa[2 * p][3]     = fu(tf32r(hi4.y * SCL));
        qa[2 * p + 1][0] = fu(tf32r(lo4.z * SCL));
        qa[2 * p + 1][1] = fu(tf32r(hi4.z * SCL));
        qa[2 * p + 1][2] = fu(tf32r(lo4.w * SCL));
        qa[2 * p + 1][3] = fu(tf32r(hi4.w * SCL));
    }

    int kj0 = rp * 4, kj1 = 4 - rp * 4, kj2 = 8 + rp * 4, kj3 = 12 - rp * 4;
    int kOff[8], vOffB[8];
    #pragma unroll
    for (int nt = 0; nt < 8; nt++) {
        kOff[nt]  = (nt * 8 + r) * 16 + c4;          // K f4 index
        vOffB[nt] = (nt * 8 + r) * VROWB + 2 * c4;   // V bf16 index
    }

    float o_[8][4] = {};
    float m0v = -1e30f, m1v = -1e30f, l0 = 0.f, l1 = 0.f;
    int nkt = qt + 1;

    // ---- pointer-increment staging ----
    int krow = t >> 4, kcc = t & 15;
    int kswz = kcc ^ ((krow & 1) * 4);
    uint32_t dstK0 = (uint32_t)__cvta_generic_to_shared(Ks4) + (krow * 16 + kswz) * 16;
    const float* pK = K + (size_t)bh * L_ * HD_ + krow * 64 + kcc * 4;
    int vrow = t >> 3, vcc = t & 7;                  // V: 64 rows x 8 chunks
    uint32_t dstV0 = (uint32_t)__cvta_generic_to_shared(VsB) + vrow * 144 + vcc * 16;
    const __nv_bfloat16* pV = V + (size_t)bh * HD_ * L_ + (size_t)vrow * L_ + vcc * 8;

    auto load_stage = [&](int stg) {
        uint32_t sK = dstK0 + stg * 16384;
        uint32_t sV = dstV0 + stg * 9216;
        #pragma unroll
        for (int i = 0; i < 8; i++)
            CPA16(sK + i * 2048, pK + i * 512);              // K rows +8
        #pragma unroll
        for (int i = 0; i < 4; i++)
            CPA16(sV + i * (16 * 144), pV + (size_t)i * 16 * L_);  // V dims +16
        pK += 64 * HD_;
        pV += 64;
    };

    load_stage(0);
    CPA_COMMIT;
    #pragma unroll 1
    for (int kt = 0; kt < nkt; kt++) {
        asm volatile("cp.async.wait_group 0;\n");
        __syncthreads();
        if (kt + 1 < nkt) {
            load_stage((kt + 1) & 1);
            CPA_COMMIT;
        }
        int kbase = kt * 64;
        if (kbase <= gqw + 15 && kbase < len) {
            const float4* ks4 = Ks4 + (kt & 1) * 1024;
            const __nv_bfloat16* vsb = VsB + (kt & 1) * (64 * VROWB);
            // ---- S = Q K^T (tf32, parity-reordered K chunks) ----
            float s[8][4] = {};
            #pragma unroll
            for (int j = 0; j < 4; j++) {
                int jo = (j == 0) ? kj0 : (j == 1) ? kj1 : (j == 2) ? kj2 : kj3;
                #pragma unroll
                for (int nt = 0; nt < 8; nt++) {
                    float4 kb = ks4[kOff[nt] + jo];
                    mma_tf32(s[nt][0], s[nt][1], s[nt][2], s[nt][3],
                             qa[2 * j][0], qa[2 * j][1], qa[2 * j][2], qa[2 * j][3],
                             fu(kb.x), fu(kb.y));
                    mma_tf32(s[nt][0], s[nt][1], s[nt][2], s[nt][3],
                             qa[2 * j + 1][0], qa[2 * j + 1][1], qa[2 * j + 1][2], qa[2 * j + 1][3],
                             fu(kb.z), fu(kb.w));
                }
            }
            // ---- masking (length + causal) ----
            int gq0 = gqw + r, gq1 = gq0 + 8;
            bool full = (kbase + 63 <= gqw) && (kbase + 64 <= len);
            if (!full) {
                #pragma unroll
                for (int nt = 0; nt < 8; nt++) {
                    int kc = kbase + nt * 8 + 2 * c4;
                    if (!(kc     <= gq0 && kc     < len)) s[nt][0] = -1e30f;
                    if (!(kc + 1 <= gq0 && kc + 1 < len)) s[nt][1] = -1e30f;
                    if (!(kc     <= gq1 && kc     < len)) s[nt][2] = -1e30f;
                    if (!(kc + 1 <= gq1 && kc + 1 < len)) s[nt][3] = -1e30f;
                }
            }
            // ---- online softmax (exp2 domain) ----
            float mx0 = -1e30f, mx1 = -1e30f;
            #pragma unroll
            for (int nt = 0; nt < 8; nt++) {
                mx0 = fmaxf(mx0, fmaxf(s[nt][0], s[nt][1]));
                mx1 = fmaxf(mx1, fmaxf(s[nt][2], s[nt][3]));
            }
            mx0 = fmaxf(mx0, __shfl_xor_sync(0xffffffffu, mx0, 1));
            mx0 = fmaxf(mx0, __shfl_xor_sync(0xffffffffu, mx0, 2));
            mx1 = fmaxf(mx1, __shfl_xor_sync(0xffffffffu, mx1, 1));
            mx1 = fmaxf(mx1, __shfl_xor_sync(0xffffffffu, mx1, 2));
            float nm0 = fmaxf(m0v, mx0), nm1 = fmaxf(m1v, mx1);
            float sc0 = ex2f(m0v - nm0), sc1 = ex2f(m1v - nm1);
            m0v = nm0; m1v = nm1;
            float rs0 = 0.f, rs1 = 0.f;
            #pragma unroll
            for (int nt = 0; nt < 8; nt++) {
                s[nt][0] = ex2f(s[nt][0] - nm0); rs0 += s[nt][0];
                s[nt][1] = ex2f(s[nt][1] - nm0); rs0 += s[nt][1];
                s[nt][2] = ex2f(s[nt][2] - nm1); rs1 += s[nt][2];
                s[nt][3] = ex2f(s[nt][3] - nm1); rs1 += s[nt][3];
            }
            rs0 += __shfl_xor_sync(0xffffffffu, rs0, 1);
            rs0 += __shfl_xor_sync(0xffffffffu, rs0, 2);
            rs1 += __shfl_xor_sync(0xffffffffu, rs1, 1);
            rs1 += __shfl_xor_sync(0xffffffffu, rs1, 2);
            l0 = l0 * sc0 + rs0;
            l1 = l1 * sc1 + rs1;
            #pragma unroll
            for (int nt = 0; nt < 8; nt++) {
                o_[nt][0] *= sc0; o_[nt][1] *= sc0;
                o_[nt][2] *= sc1; o_[nt][3] *= sc1;
            }
            // ---- O += P V  (bf16 m16n8k16; P fragments direct from s[]) ----
            #pragma unroll
            for (int g = 0; g < 4; g++) {
                uint32_t a0 = packbf(s[2 * g][0],     s[2 * g][1]);
                uint32_t a1 = packbf(s[2 * g][2],     s[2 * g][3]);
                uint32_t a2 = packbf(s[2 * g + 1][0], s[2 * g + 1][1]);
                uint32_t a3 = packbf(s[2 * g + 1][2], s[2 * g + 1][3]);
                #pragma unroll
                for (int nt = 0; nt < 8; nt++) {
                    const uint32_t* vp = (const uint32_t*)(vsb + vOffB[nt] + 16 * g);
                    uint32_t b0 = vp[0];
                    uint32_t b1 = vp[4];   // keys +8
                    mma_bf16(o_[nt][0], o_[nt][1], o_[nt][2], o_[nt][3],
                             a0, a1, a2, a3, b0, b1);
                }
            }
        }
    }

    float inv0 = 1.0f / l0, inv1 = 1.0f / l1;
    size_t ob = (size_t)bidx * L_ + gqw;
    #pragma unroll
    for (int nt = 0; nt < 8; nt++) {
        int col = head * HD_ + nt * 8 + 2 * c4;
        float2 v0 = {tf32r(o_[nt][0] * inv0), tf32r(o_[nt][1] * inv0)};
        float2 v1 = {tf32r(o_[nt][2] * inv1), tf32r(o_[nt][3] * inv1)};
        *(float2*)(O + (ob + r) * D_ + col) = v0;
        *(float2*)(O + (ob + r + 8) * D_ + col) = v1;
    }
}

// ---------------- launch ----------------
extern "C" void kernel_launch(void* const* d_in, const int* in_sizes, int n_in,
                              void* d_out, int out_size) {
    const float* x     = (const float*)d_in[0];
    const void*  pmask = d_in[1];
    const float* Wq = (const float*)d_in[3];
    const float* bq = (const float*)d_in[4];
    const float* Wk = (const float*)d_in[5];
    const float* bk = (const float*)d_in[6];
    const float* Wv = (const float*)d_in[7];
    const float* bv = (const float*)d_in[8];
    const float* Wo = (const float*)d_in[9];
    const float* bo = (const float*)d_in[10];
    const float* g_pre = (const float*)d_in[11];
    const float* b_pre = (const float*)d_in[12];
    const float* g_ln  = (const float*)d_in[13];
    const float* b_ln  = (const float*)d_in[14];
    float* out = (float*)d_out;

    float *h, *q, *k, *att, *y, *wqkv, *wo4;
    __nv_bfloat16* v;
    cudaGetSymbolAddress((void**)&h,    g_h);
    cudaGetSymbolAddress((void**)&q,    g_q);
    cudaGetSymbolAddress((void**)&k,    g_k);
    cudaGetSymbolAddress((void**)&v,    g_v);
    cudaGetSymbolAddress((void**)&att,  g_att);
    cudaGetSymbolAddress((void**)&y,    g_y);
    cudaGetSymbolAddress((void**)&wqkv, g_wqkv);
    cudaGetSymbolAddress((void**)&wo4,  g_wo4);

    const int gemm_smem = 6 * 1024 * 16;                 // 98304
    const int attn_smem = 2 * 1024 * 16 + 2 * 64 * VROWB * 2;  // 32768 + 18432 = 51200
    cudaFuncSetAttribute(tgemm_kernel,   cudaFuncAttributeMaxDynamicSharedMemorySize, gemm_smem);
    cudaFuncSetAttribute(attn_tc_kernel, cudaFuncAttributeMaxDynamicSharedMemorySize, attn_smem);

    mask_len_kernel<<<1, 256>>>((const unsigned int*)pmask);
    wround_kernel<<<(D_ * D_) / 256, 256>>>(Wq, Wk, Wv, Wo);
    ln_kernel<<<M_ / 8, 256>>>(x, g_pre, b_pre, h, 1);

    // fused QKV projection: N = 3072 (V scattered transposed bf16)
    tgemm_kernel<<<dim3(3 * D_ / 128, M_ / 128), 256, gemm_smem>>>(
        h, wqkv, bq, bk, bv, nullptr, q, k, v, 1);

    attn_tc_kernel<<<dim3(L_ / 64, B_ * H_), 128, attn_smem>>>(q, k, v, att);

    // output projection + residual
    tgemm_kernel<<<dim3(D_ / 128, M_ / 128), 256, gemm_smem>>>(
        att, wo4, bo, bo, bo, h, y, y, nullptr, 0);

    ln_kernel<<<M_ / 8, 256>>>(y, g_ln, b_ln, out, 0);
}